// round 2
// baseline (speedup 1.0000x reference)
#include <cuda_runtime.h>
#include <math.h>

#define HIDDEN 4096
#define NHEADS 32
#define HDIM   128
#define BB     2
#define SSEQ   2048
#define TOK    (BB * SSEQ)       /* 4096 tokens */
#define QKVW   (3 * HIDDEN)      /* 12288 */

/* Scratch (device globals: allocation-free per harness rules) */
__device__ float g_qkv[(size_t)TOK * QKVW];   /* [tok][q(4096) k(4096) v(4096)] */
__device__ float g_ctx[(size_t)TOK * HIDDEN]; /* attention context */

/* ------------------------------------------------------------------ */
/* SGEMM: C[M,N] = A[M,K] @ B[K,N] (+bias). 128x128 tile, BK=8,       */
/* 8x8 per-thread microtile, 256 threads. All dims multiples of 128.  */
/* ------------------------------------------------------------------ */
__global__ __launch_bounds__(256) void sgemm_kernel(
    const float* __restrict__ A, const float* __restrict__ B,
    const float* __restrict__ bias, float* __restrict__ C,
    int M, int N, int K)
{
    __shared__ float As[8][128];
    __shared__ float Bs[8][128];

    const int tid = threadIdx.x;
    const int cm = blockIdx.y * 128, cn = blockIdx.x * 128;
    const int arow = tid >> 1, acol = (tid & 1) * 4;
    const int brow = tid >> 5, bcol = (tid & 31) * 4;
    const int ty = tid >> 4, tx = tid & 15;

    const float* Ap = A + (size_t)(cm + arow) * K + acol;
    const float* Bp = B + (size_t)brow * N + cn + bcol;

    float acc[8][8];
#pragma unroll
    for (int i = 0; i < 8; i++)
#pragma unroll
        for (int j = 0; j < 8; j++) acc[i][j] = 0.f;

    for (int k0 = 0; k0 < K; k0 += 8) {
        float4 av = *(const float4*)Ap; Ap += 8;
        float4 bv = *(const float4*)Bp; Bp += (size_t)8 * N;
        __syncthreads();
        As[acol + 0][arow] = av.x;
        As[acol + 1][arow] = av.y;
        As[acol + 2][arow] = av.z;
        As[acol + 3][arow] = av.w;
        *(float4*)&Bs[brow][bcol] = bv;
        __syncthreads();
#pragma unroll
        for (int kk = 0; kk < 8; kk++) {
            float4 a0 = *(const float4*)&As[kk][ty * 8];
            float4 a1 = *(const float4*)&As[kk][ty * 8 + 4];
            float4 b0 = *(const float4*)&Bs[kk][tx * 8];
            float4 b1 = *(const float4*)&Bs[kk][tx * 8 + 4];
            float ra[8] = {a0.x, a0.y, a0.z, a0.w, a1.x, a1.y, a1.z, a1.w};
            float rb[8] = {b0.x, b0.y, b0.z, b0.w, b1.x, b1.y, b1.z, b1.w};
#pragma unroll
            for (int i = 0; i < 8; i++)
#pragma unroll
                for (int j = 0; j < 8; j++)
                    acc[i][j] += ra[i] * rb[j];
        }
    }

    float bj[8];
    if (bias) {
#pragma unroll
        for (int j = 0; j < 8; j++) bj[j] = bias[cn + tx * 8 + j];
    } else {
#pragma unroll
        for (int j = 0; j < 8; j++) bj[j] = 0.f;
    }
#pragma unroll
    for (int i = 0; i < 8; i++) {
        size_t row = (size_t)(cm + ty * 8 + i);
        float* cp = C + row * N + cn + tx * 8;
        *(float4*)cp = make_float4(acc[i][0] + bj[0], acc[i][1] + bj[1],
                                   acc[i][2] + bj[2], acc[i][3] + bj[3]);
        *(float4*)(cp + 4) = make_float4(acc[i][4] + bj[4], acc[i][5] + bj[5],
                                         acc[i][6] + bj[6], acc[i][7] + bj[7]);
    }
}

/* ------------------------------------------------------------------ */
/* RoPE in-place on q and k halves of g_qkv.                          */
/* grid = TOK*NHEADS blocks, 64 threads (one per freq index).         */
/* ------------------------------------------------------------------ */
__global__ __launch_bounds__(64) void rope_kernel(const int* __restrict__ positions)
{
    const int bsh = blockIdx.x;
    const int h  = bsh & (NHEADS - 1);
    const int bs = bsh >> 5;
    const int t  = threadIdx.x;              /* 0..63 */
    const int pos = positions[bs];

    /* inv_freq = 10000^(-t/64); computed in double for accuracy */
    double inv = exp(-(double)t * (9.210340371976184 / 64.0));
    double ang = (double)pos * inv;
    float c = (float)cos(ang);
    float s = (float)sin(ang);

    size_t base = (size_t)bs * QKVW + (size_t)h * HDIM;
    /* q */
    float x1 = g_qkv[base + t], x2 = g_qkv[base + 64 + t];
    g_qkv[base + t]      = x1 * c - x2 * s;
    g_qkv[base + 64 + t] = x2 * c + x1 * s;
    /* k */
    size_t kb = base + HIDDEN;
    x1 = g_qkv[kb + t]; x2 = g_qkv[kb + 64 + t];
    g_qkv[kb + t]      = x1 * c - x2 * s;
    g_qkv[kb + 64 + t] = x2 * c + x1 * s;
}

/* ------------------------------------------------------------------ */
/* Flash attention (causal). 64 queries x 64 keys per tile, d=128.    */
/* 256 threads: thread = (q_row = tid/4, d_chunk = tid%4 of 32 dims). */
/* Row pad 132 floats keeps float4 smem accesses aligned and          */
/* bank-spread; score tile padded to 66.                              */
/* ------------------------------------------------------------------ */
#define BQ   64
#define BKT  64
#define RPAD 132
#define SPAD 66

__global__ __launch_bounds__(256) void flash_kernel()
{
    extern __shared__ float sm[];
    float* Qs = sm;                   /* BQ  * RPAD */
    float* Ks = Qs + BQ * RPAD;       /* BKT * RPAD */
    float* Vs = Ks + BKT * RPAD;      /* BKT * RPAD */
    float* Ss = Vs + BKT * RPAD;      /* BQ  * SPAD */

    const int tid = threadIdx.x;
    const int q0 = blockIdx.x * BQ;
    const int h  = blockIdx.y;
    const int b  = blockIdx.z;
    const size_t tokbase = (size_t)b * SSEQ;
    const float scale = 0.08838834764831845f; /* 128^-0.5 */

    /* load Q tile (float4, coalesced) */
    for (int idx = tid; idx < BQ * (HDIM / 4); idx += 256) {
        int r = idx >> 5, c4 = (idx & 31) * 4;
        *(float4*)&Qs[r * RPAD + c4] =
            *(const float4*)&g_qkv[(tokbase + q0 + r) * QKVW + (size_t)h * HDIM + c4];
    }

    const int q = tid >> 2, dch = tid & 3;
    const int gq = q0 + q;
    float m = -INFINITY, l = 0.f;
    float4 O[8];
#pragma unroll
    for (int i = 0; i < 8; i++) O[i] = make_float4(0.f, 0.f, 0.f, 0.f);

    const int kend = q0 + BQ;   /* causal: only key tiles that intersect [0, gq] */
    for (int k0 = 0; k0 < kend; k0 += BKT) {
        __syncthreads();  /* prior-iteration reads of Ks/Vs/Ss done; Qs ready on iter 0 */
        for (int idx = tid; idx < BKT * (HDIM / 4); idx += 256) {
            int r = idx >> 5, c4 = (idx & 31) * 4;
            size_t rowb = (tokbase + k0 + r) * QKVW + (size_t)h * HDIM + c4;
            *(float4*)&Ks[r * RPAD + c4] = *(const float4*)&g_qkv[rowb + HIDDEN];
            *(float4*)&Vs[r * RPAD + c4] = *(const float4*)&g_qkv[rowb + 2 * HIDDEN];
        }
        __syncthreads();

        /* scores: 16 per thread, vectorized dot over d=128 */
        for (int idx = tid; idx < BQ * BKT; idx += 256) {
            int sq = idx >> 6, sk = idx & 63;
            const float4* qp = (const float4*)&Qs[sq * RPAD];
            const float4* kp = (const float4*)&Ks[sk * RPAD];
            float a = 0.f;
#pragma unroll
            for (int d = 0; d < 32; d++) {
                float4 x = qp[d], y = kp[d];
                a += x.x * y.x + x.y * y.y + x.z * y.z + x.w * y.w;
            }
            a *= scale;
            if (k0 + sk > q0 + sq) a = -1e30f;   /* causal mask, matches ref */
            Ss[sq * SPAD + sk] = a;
        }
        __syncthreads();

        /* online softmax row stats (4 threads per row, redundant reduce) */
        float rm = m;
#pragma unroll 8
        for (int j = 0; j < BKT; j++) rm = fmaxf(rm, Ss[q * SPAD + j]);
        float alpha = __expf(m - rm);
        float psum = 0.f;
        float pb[16];
#pragma unroll
        for (int jj = 0; jj < 16; jj++) {
            int j = dch + 4 * jj;
            float p = __expf(Ss[q * SPAD + j] - rm);
            pb[jj] = p; psum += p;
        }
        __syncthreads();            /* everyone finished reading raw scores */
#pragma unroll
        for (int jj = 0; jj < 16; jj++) Ss[q * SPAD + dch + 4 * jj] = pb[jj];
        psum += __shfl_xor_sync(0xffffffffu, psum, 1);
        psum += __shfl_xor_sync(0xffffffffu, psum, 2);
        l = l * alpha + psum;
        m = rm;
#pragma unroll
        for (int i = 0; i < 8; i++) {
            O[i].x *= alpha; O[i].y *= alpha; O[i].z *= alpha; O[i].w *= alpha;
        }
        __syncthreads();            /* P tile fully written */

        /* O += P @ V (thread owns 32 contiguous dims: dch*32 .. dch*32+31) */
        for (int k = 0; k < BKT; k++) {
            float p = Ss[q * SPAD + k];
            const float4* vp = (const float4*)&Vs[k * RPAD + dch * 32];
#pragma unroll
            for (int i = 0; i < 8; i++) {
                float4 v = vp[i];
                O[i].x += p * v.x; O[i].y += p * v.y;
                O[i].z += p * v.z; O[i].w += p * v.w;
            }
        }
    }

    float inv = 1.f / l;
    float* op = &g_ctx[(tokbase + gq) * HIDDEN + (size_t)h * HDIM + dch * 32];
#pragma unroll
    for (int i = 0; i < 8; i++) {
        *(float4*)(op + 4 * i) =
            make_float4(O[i].x * inv, O[i].y * inv, O[i].z * inv, O[i].w * inv);
    }
}

/* ------------------------------------------------------------------ */
extern "C" void kernel_launch(void* const* d_in, const int* in_sizes, int n_in,
                              void* d_out, int out_size)
{
    (void)in_sizes; (void)n_in; (void)out_size;
    const float* hs   = (const float*)d_in[0];  /* hidden_states [B,S,H]   */
    const int*   pos  = (const int*)  d_in[1];  /* positions [B,S]         */
    const float* Wqkv = (const float*)d_in[2];  /* [H, 3H]                 */
    const float* bqkv = (const float*)d_in[3];  /* [3H]                    */
    const float* Wo   = (const float*)d_in[4];  /* [H, H]                  */
    float* out = (float*)d_out;                 /* [B,S,H]                 */

    float *qkv = nullptr, *ctx = nullptr;
    cudaGetSymbolAddress((void**)&qkv, g_qkv);
    cudaGetSymbolAddress((void**)&ctx, g_ctx);

    const size_t smem_att = (size_t)(3 * BQ * RPAD + BQ * SPAD) * sizeof(float);
    cudaFuncSetAttribute(flash_kernel,
                         cudaFuncAttributeMaxDynamicSharedMemorySize,
                         (int)smem_att);

    /* 1. QKV projection + bias */
    sgemm_kernel<<<dim3(QKVW / 128, TOK / 128), 256>>>(hs, Wqkv, bqkv, qkv,
                                                       TOK, QKVW, HIDDEN);
    /* 2. RoPE on q,k in place */
    rope_kernel<<<TOK * NHEADS, 64>>>(pos);
    /* 3. causal flash attention -> ctx */
    flash_kernel<<<dim3(SSEQ / BQ, NHEADS, BB), 256, smem_att>>>();
    /* 4. output projection -> d_out */
    sgemm_kernel<<<dim3(HIDDEN / 128, TOK / 128), 256>>>(ctx, Wo, nullptr, out,
                                                         TOK, HIDDEN, HIDDEN);
}

// round 4
// speedup vs baseline: 1.6495x; 1.6495x over previous
#include <cuda_runtime.h>
#include <cuda_bf16.h>
#include <math.h>
#include <stdint.h>

#define HIDDEN 4096
#define NHEADS 32
#define HDIM   128
#define BB     2
#define SSEQ   2048
#define TOK    (BB * SSEQ)       /* 4096 tokens */
#define QKVW   (3 * HIDDEN)      /* 12288 */

#define MT  (TOK / 128)          /* 32 A row-tiles   */
#define KC  (HIDDEN / 64)        /* 64 K chunks      */
#define NTQ (QKVW / 128)         /* 96 B tiles (qkv) */
#define NTO (HIDDEN / 128)       /* 32 B tiles (o)   */
#define TILE_ELEMS 8192          /* 128x64 bf16 = 16KB */

/* ---------------- device scratch (no allocs allowed) ---------------- */
__device__ float g_qkv[(size_t)TOK * QKVW];
__device__ float g_ctx[(size_t)TOK * HIDDEN];
__device__ __align__(1024) __nv_bfloat16 g_Ahi[(size_t)MT * KC * TILE_ELEMS];
__device__ __align__(1024) __nv_bfloat16 g_Alo[(size_t)MT * KC * TILE_ELEMS];
__device__ __align__(1024) __nv_bfloat16 g_BhiQ[(size_t)NTQ * KC * TILE_ELEMS];
__device__ __align__(1024) __nv_bfloat16 g_BloQ[(size_t)NTQ * KC * TILE_ELEMS];
__device__ __align__(1024) __nv_bfloat16 g_BhiO[(size_t)NTO * KC * TILE_ELEMS];
__device__ __align__(1024) __nv_bfloat16 g_BloO[(size_t)NTO * KC * TILE_ELEMS];

/* ---------------- helpers ---------------- */
__device__ __forceinline__ uint32_t smem_u32(const void* p) {
    uint32_t a;
    asm("{ .reg .u64 t; cvta.to.shared.u64 t, %1; cvt.u32.u64 %0, t; }"
        : "=r"(a) : "l"(p));
    return a;
}
__device__ __forceinline__ uint32_t sw128(uint32_t b) { return b ^ ((b >> 3) & 0x70); }

__device__ __forceinline__ void cp16(uint32_t d, const void* s) {
    asm volatile("cp.async.cg.shared.global [%0], [%1], 16;" :: "r"(d), "l"(s));
}
#define CP_COMMIT() asm volatile("cp.async.commit_group;" ::: "memory")
template <int N> __device__ __forceinline__ void cp_wait() {
    asm volatile("cp.async.wait_group %0;" :: "n"(N) : "memory");
}

#define LDM4(r, a)                                                            \
    asm volatile("ldmatrix.sync.aligned.m8n8.x4.shared.b16 {%0,%1,%2,%3}, [%4];" \
        : "=r"((r)[0]), "=r"((r)[1]), "=r"((r)[2]), "=r"((r)[3]) : "r"(a))

#define MMA16816(c, a, b0, b1)                                                \
    asm volatile("mma.sync.aligned.m16n8k16.row.col.f32.bf16.bf16.f32 "       \
        "{%0,%1,%2,%3}, {%4,%5,%6,%7}, {%8,%9}, {%0,%1,%2,%3};"               \
        : "+f"((c)[0]), "+f"((c)[1]), "+f"((c)[2]), "+f"((c)[3])              \
        : "r"((a)[0]), "r"((a)[1]), "r"((a)[2]), "r"((a)[3]), "r"(b0), "r"(b1))

/* ------------------------------------------------------------------ */
/* pack_a: fp32 [rows x 4096] -> swizzled bf16 hi/lo tile panels       */
/* ------------------------------------------------------------------ */
__global__ __launch_bounds__(256) void pack_a(const float* __restrict__ A,
                                              __nv_bfloat16* __restrict__ Oh,
                                              __nv_bfloat16* __restrict__ Ol)
{
    const int kc = blockIdx.x, mt = blockIdx.y;
    char* oh = (char*)(Oh + ((size_t)mt * KC + kc) * TILE_ELEMS);
    char* ol = (char*)(Ol + ((size_t)mt * KC + kc) * TILE_ELEMS);
    for (int u = threadIdx.x; u < 1024; u += 256) {
        int r = u >> 3, c8 = (u & 7) * 8;
        const float* src = A + ((size_t)(mt * 128 + r)) * HIDDEN + kc * 64 + c8;
        float4 v0 = *(const float4*)src, v1 = *(const float4*)(src + 4);
        float v[8] = {v0.x, v0.y, v0.z, v0.w, v1.x, v1.y, v1.z, v1.w};
        __align__(16) __nv_bfloat16 h[8], l[8];
#pragma unroll
        for (int j = 0; j < 8; j++) {
            h[j] = __float2bfloat16(v[j]);
            l[j] = __float2bfloat16(v[j] - __bfloat162float(h[j]));
        }
        uint32_t off = sw128((uint32_t)(r * 128 + c8 * 2));
        *(uint4*)(oh + off) = *(const uint4*)h;
        *(uint4*)(ol + off) = *(const uint4*)l;
    }
}

/* ------------------------------------------------------------------ */
/* pack_bt: W [K x N] fp32 -> transposed swizzled bf16 hi/lo panels    */
/* panel tile: 128 (n) rows x 64 (k) cols                              */
/* ------------------------------------------------------------------ */
__global__ __launch_bounds__(256) void pack_bt(const float* __restrict__ W, int Ntot,
                                               __nv_bfloat16* __restrict__ Oh,
                                               __nv_bfloat16* __restrict__ Ol)
{
    __shared__ float ts[64 * 129];
    const int nt = blockIdx.x, kc = blockIdx.y;
    for (int idx = threadIdx.x; idx < 64 * 128; idx += 256) {
        int k = idx >> 7, n = idx & 127;
        ts[k * 129 + n] = W[(size_t)(kc * 64 + k) * Ntot + nt * 128 + n];
    }
    __syncthreads();
    char* oh = (char*)(Oh + ((size_t)nt * KC + kc) * TILE_ELEMS);
    char* ol = (char*)(Ol + ((size_t)nt * KC + kc) * TILE_ELEMS);
    for (int u = threadIdx.x; u < 1024; u += 256) {
        int n = u >> 3, k8 = (u & 7) * 8;
        __align__(16) __nv_bfloat16 h[8], l[8];
#pragma unroll
        for (int j = 0; j < 8; j++) {
            float v = ts[(k8 + j) * 129 + n];
            h[j] = __float2bfloat16(v);
            l[j] = __float2bfloat16(v - __bfloat162float(h[j]));
        }
        uint32_t off = sw128((uint32_t)(n * 128 + k8 * 2));
        *(uint4*)(oh + off) = *(const uint4*)h;
        *(uint4*)(ol + off) = *(const uint4*)l;
    }
}

/* ------------------------------------------------------------------ */
/* mma.sync GEMM: C[128mt][128nt] = A @ B^T, bf16x3 split, fp32 acc.   */
/* 256 threads = 8 warps (2m x 4n); warp tile 64x32; m16n8k16 HMMA.    */
/* Double-buffered cp.async stages of 64KB (Ah|Al|Bh|Bl 16KB each).    */
/* ------------------------------------------------------------------ */
#define NSTG 2
#define STAGE_BYTES 65536
#define GEMM_SMEM (NSTG * STAGE_BYTES)

__global__ __launch_bounds__(256) void gemm_mma(
    const __nv_bfloat16* __restrict__ Ah, const __nv_bfloat16* __restrict__ Al,
    const __nv_bfloat16* __restrict__ Bh, const __nv_bfloat16* __restrict__ Bl,
    const float* __restrict__ bias, float* __restrict__ C, int Ntot)
{
    extern __shared__ char smem[];
    const uint32_t sb = smem_u32(smem);
    const int tid = threadIdx.x, wid = tid >> 5, lane = tid & 31;
    const int wm = wid & 1, wn = wid >> 1;
    const int nt = blockIdx.x, mt = blockIdx.y;

    const char* srcs[4] = {
        (const char*)(Ah + (size_t)mt * KC * TILE_ELEMS),
        (const char*)(Al + (size_t)mt * KC * TILE_ELEMS),
        (const char*)(Bh + (size_t)nt * KC * TILE_ELEMS),
        (const char*)(Bl + (size_t)nt * KC * TILE_ELEMS)};

    float acc[4][4][4];
#pragma unroll
    for (int i = 0; i < 4; i++)
#pragma unroll
        for (int j = 0; j < 4; j++)
#pragma unroll
            for (int q = 0; q < 4; q++) acc[i][j][q] = 0.f;

    /* per-thread ldmatrix addresses (row part), reused every stage */
    int rowA[4]; uint32_t offA[4];
#pragma unroll
    for (int mt2 = 0; mt2 < 4; mt2++) {
        rowA[mt2] = wm * 64 + mt2 * 16 + (lane & 15);
        offA[mt2] = (uint32_t)rowA[mt2] * 128;
    }
    const uint32_t cbA_base = (uint32_t)((lane >> 4) << 4);
    int rowB[2]; uint32_t offB[2];
#pragma unroll
    for (int np = 0; np < 2; np++) {
        rowB[np] = wn * 32 + np * 16 + ((lane & 7) | ((lane >> 4) << 3));
        offB[np] = (uint32_t)rowB[np] * 128;
    }
    const uint32_t cbB_base = (uint32_t)(((lane >> 3) & 1) << 4);

    auto copy_stage = [&](int j, int s) {
        size_t o = (size_t)j * 16384;
#pragma unroll
        for (int r = 0; r < 4; r++) {
            const char* src = srcs[r] + o + tid * 16;
            uint32_t dst = sb + s * STAGE_BYTES + r * 16384 + tid * 16;
#pragma unroll
            for (int it = 0; it < 4; it++)
                cp16(dst + it * 4096, src + (size_t)it * 4096);
        }
    };

    copy_stage(0, 0); CP_COMMIT();

    for (int i = 0; i < KC; i++) {
        int s = i & 1;
        if (i + 1 < KC) { copy_stage(i + 1, s ^ 1); CP_COMMIT(); cp_wait<1>(); }
        else            { cp_wait<0>(); }
        __syncthreads();

        const uint32_t aHi = sb + s * STAGE_BYTES;
        const uint32_t aLo = aHi + 16384;
        const uint32_t bHi = aHi + 32768;
        const uint32_t bLo = aHi + 49152;

#pragma unroll
        for (int ks = 0; ks < 4; ks++) {
            uint32_t ah[4][4], al[4][4];
#pragma unroll
            for (int mt2 = 0; mt2 < 4; mt2++) {
                uint32_t cb = (uint32_t)(ks * 32) + cbA_base;
                uint32_t off = offA[mt2] + (cb ^ (((uint32_t)rowA[mt2] & 7) << 4));
                LDM4(ah[mt2], aHi + off);
                LDM4(al[mt2], aLo + off);
            }
            uint32_t bh[4][2], bl[4][2];
#pragma unroll
            for (int np = 0; np < 2; np++) {
                uint32_t cb = (uint32_t)(ks * 32) + cbB_base;
                uint32_t off = offB[np] + (cb ^ (((uint32_t)rowB[np] & 7) << 4));
                uint32_t t[4];
                LDM4(t, bHi + off);
                bh[np * 2][0] = t[0]; bh[np * 2][1] = t[1];
                bh[np * 2 + 1][0] = t[2]; bh[np * 2 + 1][1] = t[3];
                LDM4(t, bLo + off);
                bl[np * 2][0] = t[0]; bl[np * 2][1] = t[1];
                bl[np * 2 + 1][0] = t[2]; bl[np * 2 + 1][1] = t[3];
            }
#pragma unroll
            for (int mt2 = 0; mt2 < 4; mt2++)
#pragma unroll
                for (int nt2 = 0; nt2 < 4; nt2++) {
                    MMA16816(acc[mt2][nt2], ah[mt2], bh[nt2][0], bh[nt2][1]);
                    MMA16816(acc[mt2][nt2], ah[mt2], bl[nt2][0], bl[nt2][1]);
                    MMA16816(acc[mt2][nt2], al[mt2], bh[nt2][0], bh[nt2][1]);
                }
        }
        __syncthreads();
    }

    /* epilogue */
    const int r0 = mt * 128 + wm * 64 + (lane >> 2);
    const int c0 = nt * 128 + wn * 32 + (lane & 3) * 2;
#pragma unroll
    for (int mt2 = 0; mt2 < 4; mt2++) {
#pragma unroll
        for (int nt2 = 0; nt2 < 4; nt2++) {
            int row = r0 + mt2 * 16;
            int col = c0 + nt2 * 8;
            float b0 = 0.f, b1 = 0.f;
            if (bias) { b0 = bias[col]; b1 = bias[col + 1]; }
            float2* p0 = (float2*)&C[(size_t)row * Ntot + col];
            *p0 = make_float2(acc[mt2][nt2][0] + b0, acc[mt2][nt2][1] + b1);
            float2* p1 = (float2*)&C[(size_t)(row + 8) * Ntot + col];
            *p1 = make_float2(acc[mt2][nt2][2] + b0, acc[mt2][nt2][3] + b1);
        }
    }
}

/* ------------------------------------------------------------------ */
/* RoPE in-place on q and k halves of g_qkv.                          */
/* ------------------------------------------------------------------ */
__global__ __launch_bounds__(64) void rope_kernel(const int* __restrict__ positions)
{
    const int bsh = blockIdx.x;
    const int h  = bsh & (NHEADS - 1);
    const int bs = bsh >> 5;
    const int t  = threadIdx.x;
    const int pos = positions[bs];

    double inv = exp(-(double)t * (9.210340371976184 / 64.0));
    double ang = (double)pos * inv;
    float c = (float)cos(ang);
    float s = (float)sin(ang);

    size_t base = (size_t)bs * QKVW + (size_t)h * HDIM;
    float x1 = g_qkv[base + t], x2 = g_qkv[base + 64 + t];
    g_qkv[base + t]      = x1 * c - x2 * s;
    g_qkv[base + 64 + t] = x2 * c + x1 * s;
    size_t kb = base + HIDDEN;
    x1 = g_qkv[kb + t]; x2 = g_qkv[kb + 64 + t];
    g_qkv[kb + t]      = x1 * c - x2 * s;
    g_qkv[kb + 64 + t] = x2 * c + x1 * s;
}

/* ------------------------------------------------------------------ */
/* Flash attention (causal), fp32 — unchanged.                        */
/* ------------------------------------------------------------------ */
#define BQ   64
#define BKT  64
#define RPAD 132
#define SPAD 66

__global__ __launch_bounds__(256) void flash_kernel()
{
    extern __shared__ float sm[];
    float* Qs = sm;
    float* Ks = Qs + BQ * RPAD;
    float* Vs = Ks + BKT * RPAD;
    float* Ss = Vs + BKT * RPAD;

    const int tid = threadIdx.x;
    const int q0 = blockIdx.x * BQ;
    const int h  = blockIdx.y;
    const int b  = blockIdx.z;
    const size_t tokbase = (size_t)b * SSEQ;
    const float scale = 0.08838834764831845f;

    for (int idx = tid; idx < BQ * (HDIM / 4); idx += 256) {
        int r = idx >> 5, c4 = (idx & 31) * 4;
        *(float4*)&Qs[r * RPAD + c4] =
            *(const float4*)&g_qkv[(tokbase + q0 + r) * QKVW + (size_t)h * HDIM + c4];
    }

    const int q = tid >> 2, dch = tid & 3;
    const int gq = q0 + q;
    float m = -INFINITY, l = 0.f;
    float4 O[8];
#pragma unroll
    for (int i = 0; i < 8; i++) O[i] = make_float4(0.f, 0.f, 0.f, 0.f);

    const int kend = q0 + BQ;
    for (int k0 = 0; k0 < kend; k0 += BKT) {
        __syncthreads();
        for (int idx = tid; idx < BKT * (HDIM / 4); idx += 256) {
            int r = idx >> 5, c4 = (idx & 31) * 4;
            size_t rowb = (tokbase + k0 + r) * QKVW + (size_t)h * HDIM + c4;
            *(float4*)&Ks[r * RPAD + c4] = *(const float4*)&g_qkv[rowb + HIDDEN];
            *(float4*)&Vs[r * RPAD + c4] = *(const float4*)&g_qkv[rowb + 2 * HIDDEN];
        }
        __syncthreads();

        for (int idx = tid; idx < BQ * BKT; idx += 256) {
            int sq = idx >> 6, sk = idx & 63;
            const float4* qp = (const float4*)&Qs[sq * RPAD];
            const float4* kp = (const float4*)&Ks[sk * RPAD];
            float a = 0.f;
#pragma unroll
            for (int d = 0; d < 32; d++) {
                float4 x = qp[d], y = kp[d];
                a += x.x * y.x + x.y * y.y + x.z * y.z + x.w * y.w;
            }
            a *= scale;
            if (k0 + sk > q0 + sq) a = -1e30f;
            Ss[sq * SPAD + sk] = a;
        }
        __syncthreads();

        float rm = m;
#pragma unroll 8
        for (int j = 0; j < BKT; j++) rm = fmaxf(rm, Ss[q * SPAD + j]);
        float alpha = __expf(m - rm);
        float psum = 0.f;
        float pb[16];
#pragma unroll
        for (int jj = 0; jj < 16; jj++) {
            int j = dch + 4 * jj;
            float p = __expf(Ss[q * SPAD + j] - rm);
            pb[jj] = p; psum += p;
        }
        __syncthreads();
#pragma unroll
        for (int jj = 0; jj < 16; jj++) Ss[q * SPAD + dch + 4 * jj] = pb[jj];
        psum += __shfl_xor_sync(0xffffffffu, psum, 1);
        psum += __shfl_xor_sync(0xffffffffu, psum, 2);
        l = l * alpha + psum;
        m = rm;
#pragma unroll
        for (int i = 0; i < 8; i++) {
            O[i].x *= alpha; O[i].y *= alpha; O[i].z *= alpha; O[i].w *= alpha;
        }
        __syncthreads();

        for (int k = 0; k < BKT; k++) {
            float p = Ss[q * SPAD + k];
            const float4* vp = (const float4*)&Vs[k * RPAD + dch * 32];
#pragma unroll
            for (int i = 0; i < 8; i++) {
                float4 v = vp[i];
                O[i].x += p * v.x; O[i].y += p * v.y;
                O[i].z += p * v.z; O[i].w += p * v.w;
            }
        }
    }

    float inv = 1.f / l;
    float* op = &g_ctx[(tokbase + gq) * HIDDEN + (size_t)h * HDIM + dch * 32];
#pragma unroll
    for (int i = 0; i < 8; i++) {
        *(float4*)(op + 4 * i) =
            make_float4(O[i].x * inv, O[i].y * inv, O[i].z * inv, O[i].w * inv);
    }
}

/* ------------------------------------------------------------------ */
extern "C" void kernel_launch(void* const* d_in, const int* in_sizes, int n_in,
                              void* d_out, int out_size)
{
    (void)in_sizes; (void)n_in; (void)out_size;
    const float* hs   = (const float*)d_in[0];
    const int*   pos  = (const int*)  d_in[1];
    const float* Wqkv = (const float*)d_in[2];
    const float* bqkv = (const float*)d_in[3];
    const float* Wo   = (const float*)d_in[4];
    float* out = (float*)d_out;

    float *qkv, *ctx;
    __nv_bfloat16 *ahi, *alo, *bhiq, *bloq, *bhio, *bloo;
    cudaGetSymbolAddress((void**)&qkv,  g_qkv);
    cudaGetSymbolAddress((void**)&ctx,  g_ctx);
    cudaGetSymbolAddress((void**)&ahi,  g_Ahi);
    cudaGetSymbolAddress((void**)&alo,  g_Alo);
    cudaGetSymbolAddress((void**)&bhiq, g_BhiQ);
    cudaGetSymbolAddress((void**)&bloq, g_BloQ);
    cudaGetSymbolAddress((void**)&bhio, g_BhiO);
    cudaGetSymbolAddress((void**)&bloo, g_BloO);

    cudaFuncSetAttribute(gemm_mma,
                         cudaFuncAttributeMaxDynamicSharedMemorySize, GEMM_SMEM);
    const size_t smem_att = (size_t)(3 * BQ * RPAD + BQ * SPAD) * sizeof(float);
    cudaFuncSetAttribute(flash_kernel,
                         cudaFuncAttributeMaxDynamicSharedMemorySize, (int)smem_att);

    /* 1. pack inputs + weights into swizzled bf16 hi/lo tile panels */
    pack_a<<<dim3(KC, MT), 256>>>(hs, ahi, alo);
    pack_bt<<<dim3(NTQ, KC), 256>>>(Wqkv, QKVW, bhiq, bloq);

    /* 2. QKV projection on HMMA tensor cores (+bias) */
    gemm_mma<<<dim3(NTQ, MT), 256, GEMM_SMEM>>>(ahi, alo, bhiq, bloq,
                                                bqkv, qkv, QKVW);
    /* 3. RoPE in place */
    rope_kernel<<<TOK * NHEADS, 64>>>(pos);

    /* 4. causal flash attention -> ctx */
    flash_kernel<<<dim3(SSEQ / BQ, NHEADS, BB), 256, smem_att>>>();

    /* 5. O projection */
    pack_a<<<dim3(KC, MT), 256>>>(ctx, ahi, alo);
    pack_bt<<<dim3(NTO, KC), 256>>>(Wo, HIDDEN, bhio, bloo);
    gemm_mma<<<dim3(NTO, MT), 256, GEMM_SMEM>>>(ahi, alo, bhio, bloo,
                                                nullptr, out, HIDDEN);
}

// round 5
// speedup vs baseline: 4.9674x; 3.0114x over previous
#include <cuda_runtime.h>
#include <cuda_bf16.h>
#include <math.h>
#include <stdint.h>

#define HIDDEN 4096
#define NHEADS 32
#define HDIM   128
#define BB     2
#define SSEQ   2048
#define TOK    (BB * SSEQ)
#define QKVW   (3 * HIDDEN)

#define MT  (TOK / 128)
#define KC  (HIDDEN / 64)
#define NTQ (QKVW / 128)
#define NTO (HIDDEN / 128)
#define TILE_ELEMS 8192

/* ---------------- device scratch ---------------- */
__device__ float g_qkv[(size_t)TOK * QKVW];
__device__ float g_ctx[(size_t)TOK * HIDDEN];
__device__ __align__(1024) __nv_bfloat16 g_Ahi[(size_t)MT * KC * TILE_ELEMS];
__device__ __align__(1024) __nv_bfloat16 g_Alo[(size_t)MT * KC * TILE_ELEMS];
__device__ __align__(1024) __nv_bfloat16 g_BhiQ[(size_t)NTQ * KC * TILE_ELEMS];
__device__ __align__(1024) __nv_bfloat16 g_BloQ[(size_t)NTQ * KC * TILE_ELEMS];
__device__ __align__(1024) __nv_bfloat16 g_BhiO[(size_t)NTO * KC * TILE_ELEMS];
__device__ __align__(1024) __nv_bfloat16 g_BloO[(size_t)NTO * KC * TILE_ELEMS];

/* ---------------- helpers ---------------- */
__device__ __forceinline__ uint32_t smem_u32(const void* p) {
    uint32_t a;
    asm("{ .reg .u64 t; cvta.to.shared.u64 t, %1; cvt.u32.u64 %0, t; }"
        : "=r"(a) : "l"(p));
    return a;
}
__device__ __forceinline__ uint32_t sw128(uint32_t b) { return b ^ ((b >> 3) & 0x70); }

__device__ __forceinline__ void cp16(uint32_t d, const void* s) {
    asm volatile("cp.async.cg.shared.global [%0], [%1], 16;" :: "r"(d), "l"(s));
}
#define CP_COMMIT() asm volatile("cp.async.commit_group;" ::: "memory")
template <int N> __device__ __forceinline__ void cp_wait() {
    asm volatile("cp.async.wait_group %0;" :: "n"(N) : "memory");
}

#define LDM4(r, a)                                                            \
    asm volatile("ldmatrix.sync.aligned.m8n8.x4.shared.b16 {%0,%1,%2,%3}, [%4];" \
        : "=r"((r)[0]), "=r"((r)[1]), "=r"((r)[2]), "=r"((r)[3]) : "r"(a))
#define LDM4T(r, a)                                                           \
    asm volatile("ldmatrix.sync.aligned.m8n8.x4.trans.shared.b16 {%0,%1,%2,%3}, [%4];" \
        : "=r"((r)[0]), "=r"((r)[1]), "=r"((r)[2]), "=r"((r)[3]) : "r"(a))

#define MMA16816(c, a, b0, b1)                                                \
    asm volatile("mma.sync.aligned.m16n8k16.row.col.f32.bf16.bf16.f32 "       \
        "{%0,%1,%2,%3}, {%4,%5,%6,%7}, {%8,%9}, {%0,%1,%2,%3};"               \
        : "+f"((c)[0]), "+f"((c)[1]), "+f"((c)[2]), "+f"((c)[3])              \
        : "r"((a)[0]), "r"((a)[1]), "r"((a)[2]), "r"((a)[3]), "r"(b0), "r"(b1))

__device__ __forceinline__ uint32_t b2(__nv_bfloat16 a, __nv_bfloat16 b) {
    __nv_bfloat162 t; t.x = a; t.y = b;
    return *(uint32_t*)&t;
}

/* ------------------------------------------------------------------ */
/* pack_a / pack_bt: unchanged from round 4                            */
/* ------------------------------------------------------------------ */
__global__ __launch_bounds__(256) void pack_a(const float* __restrict__ A,
                                              __nv_bfloat16* __restrict__ Oh,
                                              __nv_bfloat16* __restrict__ Ol)
{
    const int kc = blockIdx.x, mt = blockIdx.y;
    char* oh = (char*)(Oh + ((size_t)mt * KC + kc) * TILE_ELEMS);
    char* ol = (char*)(Ol + ((size_t)mt * KC + kc) * TILE_ELEMS);
    for (int u = threadIdx.x; u < 1024; u += 256) {
        int r = u >> 3, c8 = (u & 7) * 8;
        const float* src = A + ((size_t)(mt * 128 + r)) * HIDDEN + kc * 64 + c8;
        float4 v0 = *(const float4*)src, v1 = *(const float4*)(src + 4);
        float v[8] = {v0.x, v0.y, v0.z, v0.w, v1.x, v1.y, v1.z, v1.w};
        __align__(16) __nv_bfloat16 h[8], l[8];
#pragma unroll
        for (int j = 0; j < 8; j++) {
            h[j] = __float2bfloat16(v[j]);
            l[j] = __float2bfloat16(v[j] - __bfloat162float(h[j]));
        }
        uint32_t off = sw128((uint32_t)(r * 128 + c8 * 2));
        *(uint4*)(oh + off) = *(const uint4*)h;
        *(uint4*)(ol + off) = *(const uint4*)l;
    }
}

__global__ __launch_bounds__(256) void pack_bt(const float* __restrict__ W, int Ntot,
                                               __nv_bfloat16* __restrict__ Oh,
                                               __nv_bfloat16* __restrict__ Ol)
{
    __shared__ float ts[64 * 129];
    const int nt = blockIdx.x, kc = blockIdx.y;
    for (int idx = threadIdx.x; idx < 64 * 128; idx += 256) {
        int k = idx >> 7, n = idx & 127;
        ts[k * 129 + n] = W[(size_t)(kc * 64 + k) * Ntot + nt * 128 + n];
    }
    __syncthreads();
    char* oh = (char*)(Oh + ((size_t)nt * KC + kc) * TILE_ELEMS);
    char* ol = (char*)(Ol + ((size_t)nt * KC + kc) * TILE_ELEMS);
    for (int u = threadIdx.x; u < 1024; u += 256) {
        int n = u >> 3, k8 = (u & 7) * 8;
        __align__(16) __nv_bfloat16 h[8], l[8];
#pragma unroll
        for (int j = 0; j < 8; j++) {
            float v = ts[(k8 + j) * 129 + n];
            h[j] = __float2bfloat16(v);
            l[j] = __float2bfloat16(v - __bfloat162float(h[j]));
        }
        uint32_t off = sw128((uint32_t)(n * 128 + k8 * 2));
        *(uint4*)(oh + off) = *(const uint4*)h;
        *(uint4*)(ol + off) = *(const uint4*)l;
    }
}

/* ------------------------------------------------------------------ */
/* mma.sync GEMM (unchanged from round 4)                              */
/* ------------------------------------------------------------------ */
#define NSTG 2
#define STAGE_BYTES 65536
#define GEMM_SMEM (NSTG * STAGE_BYTES)

__global__ __launch_bounds__(256) void gemm_mma(
    const __nv_bfloat16* __restrict__ Ah, const __nv_bfloat16* __restrict__ Al,
    const __nv_bfloat16* __restrict__ Bh, const __nv_bfloat16* __restrict__ Bl,
    const float* __restrict__ bias, float* __restrict__ C, int Ntot)
{
    extern __shared__ char smem[];
    const uint32_t sb = smem_u32(smem);
    const int tid = threadIdx.x, wid = tid >> 5, lane = tid & 31;
    const int wm = wid & 1, wn = wid >> 1;
    const int nt = blockIdx.x, mt = blockIdx.y;

    const char* srcs[4] = {
        (const char*)(Ah + (size_t)mt * KC * TILE_ELEMS),
        (const char*)(Al + (size_t)mt * KC * TILE_ELEMS),
        (const char*)(Bh + (size_t)nt * KC * TILE_ELEMS),
        (const char*)(Bl + (size_t)nt * KC * TILE_ELEMS)};

    float acc[4][4][4];
#pragma unroll
    for (int i = 0; i < 4; i++)
#pragma unroll
        for (int j = 0; j < 4; j++)
#pragma unroll
            for (int q = 0; q < 4; q++) acc[i][j][q] = 0.f;

    int rowA[4]; uint32_t offA[4];
#pragma unroll
    for (int mt2 = 0; mt2 < 4; mt2++) {
        rowA[mt2] = wm * 64 + mt2 * 16 + (lane & 15);
        offA[mt2] = (uint32_t)rowA[mt2] * 128;
    }
    const uint32_t cbA_base = (uint32_t)((lane >> 4) << 4);
    int rowB[2]; uint32_t offB[2];
#pragma unroll
    for (int np = 0; np < 2; np++) {
        rowB[np] = wn * 32 + np * 16 + ((lane & 7) | ((lane >> 4) << 3));
        offB[np] = (uint32_t)rowB[np] * 128;
    }
    const uint32_t cbB_base = (uint32_t)(((lane >> 3) & 1) << 4);

    auto copy_stage = [&](int j, int s) {
        size_t o = (size_t)j * 16384;
#pragma unroll
        for (int r = 0; r < 4; r++) {
            const char* src = srcs[r] + o + tid * 16;
            uint32_t dst = sb + s * STAGE_BYTES + r * 16384 + tid * 16;
#pragma unroll
            for (int it = 0; it < 4; it++)
                cp16(dst + it * 4096, src + (size_t)it * 4096);
        }
    };

    copy_stage(0, 0); CP_COMMIT();

    for (int i = 0; i < KC; i++) {
        int s = i & 1;
        if (i + 1 < KC) { copy_stage(i + 1, s ^ 1); CP_COMMIT(); cp_wait<1>(); }
        else            { cp_wait<0>(); }
        __syncthreads();

        const uint32_t aHi = sb + s * STAGE_BYTES;
        const uint32_t aLo = aHi + 16384;
        const uint32_t bHi = aHi + 32768;
        const uint32_t bLo = aHi + 49152;

#pragma unroll
        for (int ks = 0; ks < 4; ks++) {
            uint32_t ah[4][4], al[4][4];
#pragma unroll
            for (int mt2 = 0; mt2 < 4; mt2++) {
                uint32_t cb = (uint32_t)(ks * 32) + cbA_base;
                uint32_t off = offA[mt2] + (cb ^ (((uint32_t)rowA[mt2] & 7) << 4));
                LDM4(ah[mt2], aHi + off);
                LDM4(al[mt2], aLo + off);
            }
            uint32_t bh[4][2], bl[4][2];
#pragma unroll
            for (int np = 0; np < 2; np++) {
                uint32_t cb = (uint32_t)(ks * 32) + cbB_base;
                uint32_t off = offB[np] + (cb ^ (((uint32_t)rowB[np] & 7) << 4));
                uint32_t t[4];
                LDM4(t, bHi + off);
                bh[np * 2][0] = t[0]; bh[np * 2][1] = t[1];
                bh[np * 2 + 1][0] = t[2]; bh[np * 2 + 1][1] = t[3];
                LDM4(t, bLo + off);
                bl[np * 2][0] = t[0]; bl[np * 2][1] = t[1];
                bl[np * 2 + 1][0] = t[2]; bl[np * 2 + 1][1] = t[3];
            }
#pragma unroll
            for (int mt2 = 0; mt2 < 4; mt2++)
#pragma unroll
                for (int nt2 = 0; nt2 < 4; nt2++) {
                    MMA16816(acc[mt2][nt2], ah[mt2], bh[nt2][0], bh[nt2][1]);
                    MMA16816(acc[mt2][nt2], ah[mt2], bl[nt2][0], bl[nt2][1]);
                    MMA16816(acc[mt2][nt2], al[mt2], bh[nt2][0], bh[nt2][1]);
                }
        }
        __syncthreads();
    }

    const int r0 = mt * 128 + wm * 64 + (lane >> 2);
    const int c0 = nt * 128 + wn * 32 + (lane & 3) * 2;
#pragma unroll
    for (int mt2 = 0; mt2 < 4; mt2++) {
#pragma unroll
        for (int nt2 = 0; nt2 < 4; nt2++) {
            int row = r0 + mt2 * 16;
            int col = c0 + nt2 * 8;
            float b0 = 0.f, b1 = 0.f;
            if (bias) { b0 = bias[col]; b1 = bias[col + 1]; }
            float2* p0 = (float2*)&C[(size_t)row * Ntot + col];
            *p0 = make_float2(acc[mt2][nt2][0] + b0, acc[mt2][nt2][1] + b1);
            float2* p1 = (float2*)&C[(size_t)(row + 8) * Ntot + col];
            *p1 = make_float2(acc[mt2][nt2][2] + b0, acc[mt2][nt2][3] + b1);
        }
    }
}

/* ------------------------------------------------------------------ */
/* RoPE v2: one block per token; 64 dp sincos computed once in smem,  */
/* applied to all 32 heads (q and k).                                  */
/* ------------------------------------------------------------------ */
__global__ __launch_bounds__(128) void rope2(const int* __restrict__ positions)
{
    __shared__ float cs[64], sn[64];
    const int tok = blockIdx.x;
    if (threadIdx.x < 64) {
        int p = positions[tok];
        double inv = exp(-(double)threadIdx.x * (9.210340371976184 / 64.0));
        double a = (double)p * inv;
        cs[threadIdx.x] = (float)cos(a);
        sn[threadIdx.x] = (float)sin(a);
    }
    __syncthreads();
    const size_t base = (size_t)tok * QKVW;
    for (int i = threadIdx.x; i < NHEADS * 64; i += 128) {
        int h = i >> 6, d = i & 63;
        float c = cs[d], s = sn[d];
        size_t o = base + (size_t)h * HDIM + d;
        float x1 = g_qkv[o], x2 = g_qkv[o + 64];
        g_qkv[o]      = x1 * c - x2 * s;
        g_qkv[o + 64] = x2 * c + x1 * s;
        o += HIDDEN;
        x1 = g_qkv[o]; x2 = g_qkv[o + 64];
        g_qkv[o]      = x1 * c - x2 * s;
        g_qkv[o + 64] = x2 * c + x1 * s;
    }
}

/* ------------------------------------------------------------------ */
/* Flash attention on HMMA. Block = 64 q-rows x (head, batch).         */
/* 4 warps, each owns 16 q-rows. Q frags in registers (hi/lo bf16),    */
/* K/V tiles converted to hi/lo bf16 in smem (pitch 272B).             */
/* S = QhKh + QhKl + QlKh;  O += PhVh + PlVh + PhVl;  fp32 accum.      */
/* ------------------------------------------------------------------ */
#define PITB   272               /* 136 bf16 = 17 x 16B, conflict-free */
#define KVTILE 17408             /* 64 * 272 */
#define FLASH_SMEM (4 * KVTILE)  /* Kh | Kl | Vh | Vl */

__global__ __launch_bounds__(128) void flash_mma()
{
    extern __shared__ char sm[];
    const uint32_t sb = smem_u32(sm);
    const uint32_t KhS = sb, KlS = sb + KVTILE, VhS = sb + 2 * KVTILE, VlS = sb + 3 * KVTILE;
    const uint32_t QhS = sb, QlS = sb + KVTILE;  /* prologue only (overlaps K) */

    const int tid = threadIdx.x, w = tid >> 5, lane = tid & 31;
    const int qt = blockIdx.x, h = blockIdx.y, b = blockIdx.z;
    const size_t tokbase = (size_t)b * SSEQ;
    const float scale = 0.08838834764831845f;

    /* ---- load Q tile -> hi/lo bf16 smem ---- */
    for (int i = tid; i < 64 * 32; i += 128) {
        int r = i >> 5, c4 = i & 31;
        float4 v = *(const float4*)&g_qkv[(tokbase + qt * 64 + r) * QKVW +
                                          (size_t)h * HDIM + c4 * 4];
        __nv_bfloat16 hx = __float2bfloat16(v.x), hy = __float2bfloat16(v.y);
        __nv_bfloat16 hz = __float2bfloat16(v.z), hw = __float2bfloat16(v.w);
        uint2 hh = make_uint2(b2(hx, hy), b2(hz, hw));
        uint2 ll = make_uint2(
            b2(__float2bfloat16(v.x - __bfloat162float(hx)),
               __float2bfloat16(v.y - __bfloat162float(hy))),
            b2(__float2bfloat16(v.z - __bfloat162float(hz)),
               __float2bfloat16(v.w - __bfloat162float(hw))));
        *(uint2*)(sm + (QhS - sb) + r * PITB + c4 * 8) = hh;
        *(uint2*)(sm + (QlS - sb) + r * PITB + c4 * 8) = ll;
    }
    __syncthreads();

    /* ---- extract Q fragments (per warp: rows w*16..w*16+15) ---- */
    uint32_t qh[8][4], ql[8][4];
    {
        const int m0 = w * 16;
#pragma unroll
        for (int kc = 0; kc < 8; kc++) {
            uint32_t addr = QhS + (uint32_t)(m0 + (lane & 15)) * PITB +
                            (uint32_t)((kc * 2 + (lane >> 4)) * 16);
            LDM4(qh[kc], addr);
            LDM4(ql[kc], addr + KVTILE);
        }
    }
    __syncthreads();

    float O[16][4];
#pragma unroll
    for (int i = 0; i < 16; i++)
#pragma unroll
        for (int c = 0; c < 4; c++) O[i][c] = 0.f;
    float mrow0 = -INFINITY, mrow1 = -INFINITY, lrow0 = 0.f, lrow1 = 0.f;

    const int r0 = lane >> 2;
    const int ncol = (lane & 3) * 2;

    for (int kt = 0; kt <= qt; kt++) {
        /* ---- load K,V tile -> hi/lo bf16 smem ---- */
        for (int i = tid; i < 64 * 32; i += 128) {
            int r = i >> 5, c4 = i & 31;
            size_t rowb = (tokbase + kt * 64 + r) * QKVW + (size_t)h * HDIM + c4 * 4;
            float4 kv = *(const float4*)&g_qkv[rowb + HIDDEN];
            float4 vv = *(const float4*)&g_qkv[rowb + 2 * HIDDEN];
            uint32_t off = r * PITB + c4 * 8;
            {
                __nv_bfloat16 hx = __float2bfloat16(kv.x), hy = __float2bfloat16(kv.y);
                __nv_bfloat16 hz = __float2bfloat16(kv.z), hw = __float2bfloat16(kv.w);
                *(uint2*)(sm + (KhS - sb) + off) = make_uint2(b2(hx, hy), b2(hz, hw));
                *(uint2*)(sm + (KlS - sb) + off) = make_uint2(
                    b2(__float2bfloat16(kv.x - __bfloat162float(hx)),
                       __float2bfloat16(kv.y - __bfloat162float(hy))),
                    b2(__float2bfloat16(kv.z - __bfloat162float(hz)),
                       __float2bfloat16(kv.w - __bfloat162float(hw))));
            }
            {
                __nv_bfloat16 hx = __float2bfloat16(vv.x), hy = __float2bfloat16(vv.y);
                __nv_bfloat16 hz = __float2bfloat16(vv.z), hw = __float2bfloat16(vv.w);
                *(uint2*)(sm + (VhS - sb) + off) = make_uint2(b2(hx, hy), b2(hz, hw));
                *(uint2*)(sm + (VlS - sb) + off) = make_uint2(
                    b2(__float2bfloat16(vv.x - __bfloat162float(hx)),
                       __float2bfloat16(vv.y - __bfloat162float(hy))),
                    b2(__float2bfloat16(vv.z - __bfloat162float(hz)),
                       __float2bfloat16(vv.w - __bfloat162float(hw))));
            }
        }
        __syncthreads();

        /* ---- S = Q K^T ---- */
        float s[8][4];
#pragma unroll
        for (int i = 0; i < 8; i++)
#pragma unroll
            for (int c = 0; c < 4; c++) s[i][c] = 0.f;

#pragma unroll
        for (int kc = 0; kc < 8; kc++) {
#pragma unroll
            for (int nc2 = 0; nc2 < 4; nc2++) {
                int nrow = nc2 * 16 + ((lane >> 4) << 3) + (lane & 7);
                int col16 = kc * 2 + ((lane >> 3) & 1);
                uint32_t addr = KhS + (uint32_t)nrow * PITB + (uint32_t)col16 * 16;
                uint32_t bh4[4], bl4[4];
                LDM4(bh4, addr);
                LDM4(bl4, addr + KVTILE);
                MMA16816(s[nc2 * 2],     qh[kc], bh4[0], bh4[1]);
                MMA16816(s[nc2 * 2],     qh[kc], bl4[0], bl4[1]);
                MMA16816(s[nc2 * 2],     ql[kc], bh4[0], bh4[1]);
                MMA16816(s[nc2 * 2 + 1], qh[kc], bh4[2], bh4[3]);
                MMA16816(s[nc2 * 2 + 1], qh[kc], bl4[2], bl4[3]);
                MMA16816(s[nc2 * 2 + 1], ql[kc], bh4[2], bh4[3]);
            }
        }

        /* ---- scale + causal mask ---- */
        const bool diag = (kt == qt);
        const int mg0 = w * 16 + r0, mg1 = mg0 + 8;
#pragma unroll
        for (int nt = 0; nt < 8; nt++) {
#pragma unroll
            for (int c = 0; c < 4; c++) s[nt][c] *= scale;
            if (diag) {
                int n0 = nt * 8 + ncol;
                if (n0     > mg0) s[nt][0] = -1e30f;
                if (n0 + 1 > mg0) s[nt][1] = -1e30f;
                if (n0     > mg1) s[nt][2] = -1e30f;
                if (n0 + 1 > mg1) s[nt][3] = -1e30f;
            }
        }

        /* ---- online softmax ---- */
        float mx0 = mrow0, mx1 = mrow1;
#pragma unroll
        for (int nt = 0; nt < 8; nt++) {
            mx0 = fmaxf(mx0, fmaxf(s[nt][0], s[nt][1]));
            mx1 = fmaxf(mx1, fmaxf(s[nt][2], s[nt][3]));
        }
        mx0 = fmaxf(mx0, __shfl_xor_sync(0xffffffffu, mx0, 1));
        mx0 = fmaxf(mx0, __shfl_xor_sync(0xffffffffu, mx0, 2));
        mx1 = fmaxf(mx1, __shfl_xor_sync(0xffffffffu, mx1, 1));
        mx1 = fmaxf(mx1, __shfl_xor_sync(0xffffffffu, mx1, 2));
        float a0 = __expf(mrow0 - mx0), a1 = __expf(mrow1 - mx1);
        mrow0 = mx0; mrow1 = mx1;
        float ps0 = 0.f, ps1 = 0.f;
#pragma unroll
        for (int nt = 0; nt < 8; nt++) {
            s[nt][0] = __expf(s[nt][0] - mx0);
            s[nt][1] = __expf(s[nt][1] - mx0);
            s[nt][2] = __expf(s[nt][2] - mx1);
            s[nt][3] = __expf(s[nt][3] - mx1);
            ps0 += s[nt][0] + s[nt][1];
            ps1 += s[nt][2] + s[nt][3];
        }
        ps0 += __shfl_xor_sync(0xffffffffu, ps0, 1);
        ps0 += __shfl_xor_sync(0xffffffffu, ps0, 2);
        ps1 += __shfl_xor_sync(0xffffffffu, ps1, 1);
        ps1 += __shfl_xor_sync(0xffffffffu, ps1, 2);
        lrow0 = lrow0 * a0 + ps0;
        lrow1 = lrow1 * a1 + ps1;
#pragma unroll
        for (int dn = 0; dn < 16; dn++) {
            O[dn][0] *= a0; O[dn][1] *= a0;
            O[dn][2] *= a1; O[dn][3] *= a1;
        }

        /* ---- O += P V ---- */
#pragma unroll
        for (int pk = 0; pk < 4; pk++) {
            uint32_t ph[4], pl[4];
#pragma unroll
            for (int half = 0; half < 2; half++) {   /* k 0-7 / 8-15 */
                int nt = pk * 2 + half;
                __nv_bfloat16 h0 = __float2bfloat16(s[nt][0]);
                __nv_bfloat16 h1 = __float2bfloat16(s[nt][1]);
                __nv_bfloat16 h2 = __float2bfloat16(s[nt][2]);
                __nv_bfloat16 h3 = __float2bfloat16(s[nt][3]);
                ph[half * 2]     = b2(h0, h1);
                ph[half * 2 + 1] = b2(h2, h3);
                pl[half * 2]     = b2(__float2bfloat16(s[nt][0] - __bfloat162float(h0)),
                                      __float2bfloat16(s[nt][1] - __bfloat162float(h1)));
                pl[half * 2 + 1] = b2(__float2bfloat16(s[nt][2] - __bfloat162float(h2)),
                                      __float2bfloat16(s[nt][3] - __bfloat162float(h3)));
            }
            /* a-frag order: {a0,a1,a2,a3} = {k0-7 r, k0-7 r+8, k8-15 r, k8-15 r+8} */
            uint32_t pa_h[4] = {ph[0], ph[1], ph[2], ph[3]};
            uint32_t pa_l[4] = {pl[0], pl[1], pl[2], pl[3]};
#pragma unroll
            for (int dn2 = 0; dn2 < 8; dn2++) {
                uint32_t addr = VhS + (uint32_t)(pk * 16 + (lane & 15)) * PITB +
                                (uint32_t)((dn2 * 2 + (lane >> 4)) * 16);
                uint32_t vh4[4], vl4[4];
                LDM4T(vh4, addr);
                LDM4T(vl4, addr + KVTILE);
                MMA16816(O[dn2 * 2],     pa_h, vh4[0], vh4[1]);
                MMA16816(O[dn2 * 2],     pa_l, vh4[0], vh4[1]);
                MMA16816(O[dn2 * 2],     pa_h, vl4[0], vl4[1]);
                MMA16816(O[dn2 * 2 + 1], pa_h, vh4[2], vh4[3]);
                MMA16816(O[dn2 * 2 + 1], pa_l, vh4[2], vh4[3]);
                MMA16816(O[dn2 * 2 + 1], pa_h, vl4[2], vl4[3]);
            }
        }
        __syncthreads();
    }

    /* ---- epilogue ---- */
    float il0 = 1.f / lrow0, il1 = 1.f / lrow1;
    const int m_glob0 = qt * 64 + w * 16 + r0;
    const int m_glob1 = m_glob0 + 8;
#pragma unroll
    for (int dn = 0; dn < 16; dn++) {
        int d = dn * 8 + ncol;
        *(float2*)&g_ctx[(tokbase + m_glob0) * HIDDEN + (size_t)h * HDIM + d] =
            make_float2(O[dn][0] * il0, O[dn][1] * il0);
        *(float2*)&g_ctx[(tokbase + m_glob1) * HIDDEN + (size_t)h * HDIM + d] =
            make_float2(O[dn][2] * il1, O[dn][3] * il1);
    }
}

/* ------------------------------------------------------------------ */
extern "C" void kernel_launch(void* const* d_in, const int* in_sizes, int n_in,
                              void* d_out, int out_size)
{
    (void)in_sizes; (void)n_in; (void)out_size;
    const float* hs   = (const float*)d_in[0];
    const int*   pos  = (const int*)  d_in[1];
    const float* Wqkv = (const float*)d_in[2];
    const float* bqkv = (const float*)d_in[3];
    const float* Wo   = (const float*)d_in[4];
    float* out = (float*)d_out;

    float *qkv, *ctx;
    __nv_bfloat16 *ahi, *alo, *bhiq, *bloq, *bhio, *bloo;
    cudaGetSymbolAddress((void**)&qkv,  g_qkv);
    cudaGetSymbolAddress((void**)&ctx,  g_ctx);
    cudaGetSymbolAddress((void**)&ahi,  g_Ahi);
    cudaGetSymbolAddress((void**)&alo,  g_Alo);
    cudaGetSymbolAddress((void**)&bhiq, g_BhiQ);
    cudaGetSymbolAddress((void**)&bloq, g_BloQ);
    cudaGetSymbolAddress((void**)&bhio, g_BhiO);
    cudaGetSymbolAddress((void**)&bloo, g_BloO);

    cudaFuncSetAttribute(gemm_mma,
                         cudaFuncAttributeMaxDynamicSharedMemorySize, GEMM_SMEM);
    cudaFuncSetAttribute(flash_mma,
                         cudaFuncAttributeMaxDynamicSharedMemorySize, FLASH_SMEM);

    /* 1. pack inputs + weights */
    pack_a<<<dim3(KC, MT), 256>>>(hs, ahi, alo);
    pack_bt<<<dim3(NTQ, KC), 256>>>(Wqkv, QKVW, bhiq, bloq);

    /* 2. QKV projection (+bias) */
    gemm_mma<<<dim3(NTQ, MT), 256, GEMM_SMEM>>>(ahi, alo, bhiq, bloq,
                                                bqkv, qkv, QKVW);
    /* 3. RoPE */
    rope2<<<TOK, 128>>>(pos);

    /* 4. causal flash attention on HMMA -> ctx */
    flash_mma<<<dim3(SSEQ / 64, NHEADS, BB), 128, FLASH_SMEM>>>();

    /* 5. O projection */
    pack_a<<<dim3(KC, MT), 256>>>(ctx, ahi, alo);
    pack_bt<<<dim3(NTO, KC), 256>>>(Wo, HIDDEN, bhio, bloo);
    gemm_mma<<<dim3(NTO, MT), 256, GEMM_SMEM>>>(ahi, alo, bhio, bloo,
                                                nullptr, out, HIDDEN);
}

// round 6
// speedup vs baseline: 7.0292x; 1.4151x over previous
#include <cuda_runtime.h>
#include <cuda_bf16.h>
#include <cuda_fp16.h>
#include <math.h>
#include <stdint.h>

#define HIDDEN 4096
#define NHEADS 32
#define HDIM   128
#define BB     2
#define SSEQ   2048
#define TOK    (BB * SSEQ)
#define QKVW   (3 * HIDDEN)

#define MT  (TOK / 128)
#define KC  (HIDDEN / 64)
#define NTQ (QKVW / 128)
#define NTO (HIDDEN / 128)
#define TILE_ELEMS 8192

/* ---------------- device scratch ---------------- */
__device__ float g_qkv[(size_t)TOK * QKVW];
__device__ float g_ctx[(size_t)TOK * HIDDEN];
__device__ __align__(1024) __half g_Ahi[(size_t)MT * KC * TILE_ELEMS];
__device__ __align__(1024) __half g_Alo[(size_t)MT * KC * TILE_ELEMS];
__device__ __align__(1024) __half g_BhQ[(size_t)NTQ * KC * TILE_ELEMS];
__device__ __align__(1024) __half g_BhO[(size_t)NTO * KC * TILE_ELEMS];

/* ---------------- helpers ---------------- */
__device__ __forceinline__ uint32_t smem_u32(const void* p) {
    uint32_t a;
    asm("{ .reg .u64 t; cvta.to.shared.u64 t, %1; cvt.u32.u64 %0, t; }"
        : "=r"(a) : "l"(p));
    return a;
}
__device__ __forceinline__ uint32_t sw128(uint32_t b) { return b ^ ((b >> 3) & 0x70); }

__device__ __forceinline__ void cp16(uint32_t d, const void* s) {
    asm volatile("cp.async.cg.shared.global [%0], [%1], 16;" :: "r"(d), "l"(s));
}
#define CP_COMMIT() asm volatile("cp.async.commit_group;" ::: "memory")
template <int N> __device__ __forceinline__ void cp_wait() {
    asm volatile("cp.async.wait_group %0;" :: "n"(N) : "memory");
}

#define LDM4(r, a)                                                            \
    asm volatile("ldmatrix.sync.aligned.m8n8.x4.shared.b16 {%0,%1,%2,%3}, [%4];" \
        : "=r"((r)[0]), "=r"((r)[1]), "=r"((r)[2]), "=r"((r)[3]) : "r"(a))
#define LDM4T(r, a)                                                           \
    asm volatile("ldmatrix.sync.aligned.m8n8.x4.trans.shared.b16 {%0,%1,%2,%3}, [%4];" \
        : "=r"((r)[0]), "=r"((r)[1]), "=r"((r)[2]), "=r"((r)[3]) : "r"(a))

/* bf16 HMMA (flash) */
#define MMA16816(c, a, b0, b1)                                                \
    asm volatile("mma.sync.aligned.m16n8k16.row.col.f32.bf16.bf16.f32 "       \
        "{%0,%1,%2,%3}, {%4,%5,%6,%7}, {%8,%9}, {%0,%1,%2,%3};"               \
        : "+f"((c)[0]), "+f"((c)[1]), "+f"((c)[2]), "+f"((c)[3])              \
        : "r"((a)[0]), "r"((a)[1]), "r"((a)[2]), "r"((a)[3]), "r"(b0), "r"(b1))

/* fp16 HMMA (projections) */
#define MMAH16816(c, a, b0, b1)                                               \
    asm volatile("mma.sync.aligned.m16n8k16.row.col.f32.f16.f16.f32 "         \
        "{%0,%1,%2,%3}, {%4,%5,%6,%7}, {%8,%9}, {%0,%1,%2,%3};"               \
        : "+f"((c)[0]), "+f"((c)[1]), "+f"((c)[2]), "+f"((c)[3])              \
        : "r"((a)[0]), "r"((a)[1]), "r"((a)[2]), "r"((a)[3]), "r"(b0), "r"(b1))

__device__ __forceinline__ uint32_t b2(__nv_bfloat16 a, __nv_bfloat16 b) {
    __nv_bfloat162 t; t.x = a; t.y = b;
    return *(uint32_t*)&t;
}

/* ------------------------------------------------------------------ */
/* pack_a: fp32 -> swizzled fp16 hi/lo tile panels                     */
/* ------------------------------------------------------------------ */
__global__ __launch_bounds__(256) void pack_a(const float* __restrict__ A,
                                              __half* __restrict__ Oh,
                                              __half* __restrict__ Ol)
{
    const int kc = blockIdx.x, mt = blockIdx.y;
    char* oh = (char*)(Oh + ((size_t)mt * KC + kc) * TILE_ELEMS);
    char* ol = (char*)(Ol + ((size_t)mt * KC + kc) * TILE_ELEMS);
    for (int u = threadIdx.x; u < 1024; u += 256) {
        int r = u >> 3, c8 = (u & 7) * 8;
        const float* src = A + ((size_t)(mt * 128 + r)) * HIDDEN + kc * 64 + c8;
        float4 v0 = *(const float4*)src, v1 = *(const float4*)(src + 4);
        float v[8] = {v0.x, v0.y, v0.z, v0.w, v1.x, v1.y, v1.z, v1.w};
        __align__(16) __half h[8], l[8];
#pragma unroll
        for (int j = 0; j < 8; j++) {
            h[j] = __float2half_rn(v[j]);
            l[j] = __float2half_rn(v[j] - __half2float(h[j]));
        }
        uint32_t off = sw128((uint32_t)(r * 128 + c8 * 2));
        *(uint4*)(oh + off) = *(const uint4*)h;
        *(uint4*)(ol + off) = *(const uint4*)l;
    }
}

/* ------------------------------------------------------------------ */
/* pack_bt: W [K x N] fp32 -> transposed swizzled fp16 panel (hi only) */
/* ------------------------------------------------------------------ */
__global__ __launch_bounds__(256) void pack_bt(const float* __restrict__ W, int Ntot,
                                               __half* __restrict__ Oh)
{
    __shared__ float ts[64 * 129];
    const int nt = blockIdx.x, kc = blockIdx.y;
    for (int idx = threadIdx.x; idx < 64 * 128; idx += 256) {
        int k = idx >> 7, n = idx & 127;
        ts[k * 129 + n] = W[(size_t)(kc * 64 + k) * Ntot + nt * 128 + n];
    }
    __syncthreads();
    char* oh = (char*)(Oh + ((size_t)nt * KC + kc) * TILE_ELEMS);
    for (int u = threadIdx.x; u < 1024; u += 256) {
        int n = u >> 3, k8 = (u & 7) * 8;
        __align__(16) __half h[8];
#pragma unroll
        for (int j = 0; j < 8; j++)
            h[j] = __float2half_rn(ts[(k8 + j) * 129 + n]);
        uint32_t off = sw128((uint32_t)(n * 128 + k8 * 2));
        *(uint4*)(oh + off) = *(const uint4*)h;
    }
}

/* ------------------------------------------------------------------ */
/* fp16x2 mma GEMM: C = A @ B^T,  A = Ah + Al (fp16), B = Bh (fp16).   */
/* 256 threads = 8 warps (2m x 4n); warp tile 64x32; f16 HMMA.         */
/* Double-buffered cp.async stages of 48KB (Ah|Al|Bh 16KB each).       */
/* ------------------------------------------------------------------ */
#define NSTG 2
#define STAGE_BYTES 49152
#define GEMM_SMEM (NSTG * STAGE_BYTES)

__global__ __launch_bounds__(256) void gemm_mma(
    const __half* __restrict__ Ah, const __half* __restrict__ Al,
    const __half* __restrict__ Bh,
    const float* __restrict__ bias, float* __restrict__ C, int Ntot)
{
    extern __shared__ char smem[];
    const uint32_t sb = smem_u32(smem);
    const int tid = threadIdx.x, wid = tid >> 5, lane = tid & 31;
    const int wm = wid & 1, wn = wid >> 1;
    const int nt = blockIdx.x, mt = blockIdx.y;

    const char* srcs[3] = {
        (const char*)(Ah + (size_t)mt * KC * TILE_ELEMS),
        (const char*)(Al + (size_t)mt * KC * TILE_ELEMS),
        (const char*)(Bh + (size_t)nt * KC * TILE_ELEMS)};

    float acc[4][4][4];
#pragma unroll
    for (int i = 0; i < 4; i++)
#pragma unroll
        for (int j = 0; j < 4; j++)
#pragma unroll
            for (int q = 0; q < 4; q++) acc[i][j][q] = 0.f;

    int rowA[4]; uint32_t offA[4];
#pragma unroll
    for (int mt2 = 0; mt2 < 4; mt2++) {
        rowA[mt2] = wm * 64 + mt2 * 16 + (lane & 15);
        offA[mt2] = (uint32_t)rowA[mt2] * 128;
    }
    const uint32_t cbA_base = (uint32_t)((lane >> 4) << 4);
    int rowB[2]; uint32_t offB[2];
#pragma unroll
    for (int np = 0; np < 2; np++) {
        rowB[np] = wn * 32 + np * 16 + ((lane & 7) | ((lane >> 4) << 3));
        offB[np] = (uint32_t)rowB[np] * 128;
    }
    const uint32_t cbB_base = (uint32_t)(((lane >> 3) & 1) << 4);

    auto copy_stage = [&](int j, int s) {
        size_t o = (size_t)j * 16384;
#pragma unroll
        for (int r = 0; r < 3; r++) {
            const char* src = srcs[r] + o + tid * 16;
            uint32_t dst = sb + s * STAGE_BYTES + r * 16384 + tid * 16;
#pragma unroll
            for (int it = 0; it < 4; it++)
                cp16(dst + it * 4096, src + (size_t)it * 4096);
        }
    };

    copy_stage(0, 0); CP_COMMIT();

    for (int i = 0; i < KC; i++) {
        int s = i & 1;
        if (i + 1 < KC) { copy_stage(i + 1, s ^ 1); CP_COMMIT(); cp_wait<1>(); }
        else            { cp_wait<0>(); }
        __syncthreads();

        const uint32_t aHi = sb + s * STAGE_BYTES;
        const uint32_t aLo = aHi + 16384;
        const uint32_t bHi = aHi + 32768;

#pragma unroll
        for (int ks = 0; ks < 4; ks++) {
            uint32_t ah[4][4], al[4][4];
#pragma unroll
            for (int mt2 = 0; mt2 < 4; mt2++) {
                uint32_t cb = (uint32_t)(ks * 32) + cbA_base;
                uint32_t off = offA[mt2] + (cb ^ (((uint32_t)rowA[mt2] & 7) << 4));
                LDM4(ah[mt2], aHi + off);
                LDM4(al[mt2], aLo + off);
            }
            uint32_t bh[4][2];
#pragma unroll
            for (int np = 0; np < 2; np++) {
                uint32_t cb = (uint32_t)(ks * 32) + cbB_base;
                uint32_t off = offB[np] + (cb ^ (((uint32_t)rowB[np] & 7) << 4));
                uint32_t t[4];
                LDM4(t, bHi + off);
                bh[np * 2][0] = t[0]; bh[np * 2][1] = t[1];
                bh[np * 2 + 1][0] = t[2]; bh[np * 2 + 1][1] = t[3];
            }
#pragma unroll
            for (int mt2 = 0; mt2 < 4; mt2++)
#pragma unroll
                for (int nt2 = 0; nt2 < 4; nt2++) {
                    MMAH16816(acc[mt2][nt2], ah[mt2], bh[nt2][0], bh[nt2][1]);
                    MMAH16816(acc[mt2][nt2], al[mt2], bh[nt2][0], bh[nt2][1]);
                }
        }
        __syncthreads();
    }

    const int r0 = mt * 128 + wm * 64 + (lane >> 2);
    const int c0 = nt * 128 + wn * 32 + (lane & 3) * 2;
#pragma unroll
    for (int mt2 = 0; mt2 < 4; mt2++) {
#pragma unroll
        for (int nt2 = 0; nt2 < 4; nt2++) {
            int row = r0 + mt2 * 16;
            int col = c0 + nt2 * 8;
            float b0 = 0.f, b1 = 0.f;
            if (bias) { b0 = bias[col]; b1 = bias[col + 1]; }
            float2* p0 = (float2*)&C[(size_t)row * Ntot + col];
            *p0 = make_float2(acc[mt2][nt2][0] + b0, acc[mt2][nt2][1] + b1);
            float2* p1 = (float2*)&C[(size_t)(row + 8) * Ntot + col];
            *p1 = make_float2(acc[mt2][nt2][2] + b0, acc[mt2][nt2][3] + b1);
        }
    }
}

/* ------------------------------------------------------------------ */
/* RoPE v2 (unchanged)                                                 */
/* ------------------------------------------------------------------ */
__global__ __launch_bounds__(128) void rope2(const int* __restrict__ positions)
{
    __shared__ float cs[64], sn[64];
    const int tok = blockIdx.x;
    if (threadIdx.x < 64) {
        int p = positions[tok];
        double inv = exp(-(double)threadIdx.x * (9.210340371976184 / 64.0));
        double a = (double)p * inv;
        cs[threadIdx.x] = (float)cos(a);
        sn[threadIdx.x] = (float)sin(a);
    }
    __syncthreads();
    const size_t base = (size_t)tok * QKVW;
    for (int i = threadIdx.x; i < NHEADS * 64; i += 128) {
        int h = i >> 6, d = i & 63;
        float c = cs[d], s = sn[d];
        size_t o = base + (size_t)h * HDIM + d;
        float x1 = g_qkv[o], x2 = g_qkv[o + 64];
        g_qkv[o]      = x1 * c - x2 * s;
        g_qkv[o + 64] = x2 * c + x1 * s;
        o += HIDDEN;
        x1 = g_qkv[o]; x2 = g_qkv[o + 64];
        g_qkv[o]      = x1 * c - x2 * s;
        g_qkv[o + 64] = x2 * c + x1 * s;
    }
}

/* ------------------------------------------------------------------ */
/* Flash attention on HMMA (unchanged from round 5, bf16x3)            */
/* ------------------------------------------------------------------ */
#define PITB   272
#define KVTILE 17408
#define FLASH_SMEM (4 * KVTILE)

__global__ __launch_bounds__(128) void flash_mma()
{
    extern __shared__ char sm[];
    const uint32_t sb = smem_u32(sm);
    const uint32_t KhS = sb, KlS = sb + KVTILE, VhS = sb + 2 * KVTILE, VlS = sb + 3 * KVTILE;
    const uint32_t QhS = sb, QlS = sb + KVTILE;

    const int tid = threadIdx.x, w = tid >> 5, lane = tid & 31;
    const int qt = blockIdx.x, h = blockIdx.y, b = blockIdx.z;
    const size_t tokbase = (size_t)b * SSEQ;
    const float scale = 0.08838834764831845f;

    for (int i = tid; i < 64 * 32; i += 128) {
        int r = i >> 5, c4 = i & 31;
        float4 v = *(const float4*)&g_qkv[(tokbase + qt * 64 + r) * QKVW +
                                          (size_t)h * HDIM + c4 * 4];
        __nv_bfloat16 hx = __float2bfloat16(v.x), hy = __float2bfloat16(v.y);
        __nv_bfloat16 hz = __float2bfloat16(v.z), hw = __float2bfloat16(v.w);
        uint2 hh = make_uint2(b2(hx, hy), b2(hz, hw));
        uint2 ll = make_uint2(
            b2(__float2bfloat16(v.x - __bfloat162float(hx)),
               __float2bfloat16(v.y - __bfloat162float(hy))),
            b2(__float2bfloat16(v.z - __bfloat162float(hz)),
               __float2bfloat16(v.w - __bfloat162float(hw))));
        *(uint2*)(sm + (QhS - sb) + r * PITB + c4 * 8) = hh;
        *(uint2*)(sm + (QlS - sb) + r * PITB + c4 * 8) = ll;
    }
    __syncthreads();

    uint32_t qh[8][4], ql[8][4];
    {
        const int m0 = w * 16;
#pragma unroll
        for (int kc = 0; kc < 8; kc++) {
            uint32_t addr = QhS + (uint32_t)(m0 + (lane & 15)) * PITB +
                            (uint32_t)((kc * 2 + (lane >> 4)) * 16);
            LDM4(qh[kc], addr);
            LDM4(ql[kc], addr + KVTILE);
        }
    }
    __syncthreads();

    float O[16][4];
#pragma unroll
    for (int i = 0; i < 16; i++)
#pragma unroll
        for (int c = 0; c < 4; c++) O[i][c] = 0.f;
    float mrow0 = -INFINITY, mrow1 = -INFINITY, lrow0 = 0.f, lrow1 = 0.f;

    const int r0 = lane >> 2;
    const int ncol = (lane & 3) * 2;

    for (int kt = 0; kt <= qt; kt++) {
        for (int i = tid; i < 64 * 32; i += 128) {
            int r = i >> 5, c4 = i & 31;
            size_t rowb = (tokbase + kt * 64 + r) * QKVW + (size_t)h * HDIM + c4 * 4;
            float4 kv = *(const float4*)&g_qkv[rowb + HIDDEN];
            float4 vv = *(const float4*)&g_qkv[rowb + 2 * HIDDEN];
            uint32_t off = r * PITB + c4 * 8;
            {
                __nv_bfloat16 hx = __float2bfloat16(kv.x), hy = __float2bfloat16(kv.y);
                __nv_bfloat16 hz = __float2bfloat16(kv.z), hw = __float2bfloat16(kv.w);
                *(uint2*)(sm + (KhS - sb) + off) = make_uint2(b2(hx, hy), b2(hz, hw));
                *(uint2*)(sm + (KlS - sb) + off) = make_uint2(
                    b2(__float2bfloat16(kv.x - __bfloat162float(hx)),
                       __float2bfloat16(kv.y - __bfloat162float(hy))),
                    b2(__float2bfloat16(kv.z - __bfloat162float(hz)),
                       __float2bfloat16(kv.w - __bfloat162float(hw))));
            }
            {
                __nv_bfloat16 hx = __float2bfloat16(vv.x), hy = __float2bfloat16(vv.y);
                __nv_bfloat16 hz = __float2bfloat16(vv.z), hw = __float2bfloat16(vv.w);
                *(uint2*)(sm + (VhS - sb) + off) = make_uint2(b2(hx, hy), b2(hz, hw));
                *(uint2*)(sm + (VlS - sb) + off) = make_uint2(
                    b2(__float2bfloat16(vv.x - __bfloat162float(hx)),
                       __float2bfloat16(vv.y - __bfloat162float(hy))),
                    b2(__float2bfloat16(vv.z - __bfloat162float(hz)),
                       __float2bfloat16(vv.w - __bfloat162float(hw))));
            }
        }
        __syncthreads();

        float s[8][4];
#pragma unroll
        for (int i = 0; i < 8; i++)
#pragma unroll
            for (int c = 0; c < 4; c++) s[i][c] = 0.f;

#pragma unroll
        for (int kc = 0; kc < 8; kc++) {
#pragma unroll
            for (int nc2 = 0; nc2 < 4; nc2++) {
                int nrow = nc2 * 16 + ((lane >> 4) << 3) + (lane & 7);
                int col16 = kc * 2 + ((lane >> 3) & 1);
                uint32_t addr = KhS + (uint32_t)nrow * PITB + (uint32_t)col16 * 16;
                uint32_t bh4[4], bl4[4];
                LDM4(bh4, addr);
                LDM4(bl4, addr + KVTILE);
                MMA16816(s[nc2 * 2],     qh[kc], bh4[0], bh4[1]);
                MMA16816(s[nc2 * 2],     qh[kc], bl4[0], bl4[1]);
                MMA16816(s[nc2 * 2],     ql[kc], bh4[0], bh4[1]);
                MMA16816(s[nc2 * 2 + 1], qh[kc], bh4[2], bh4[3]);
                MMA16816(s[nc2 * 2 + 1], qh[kc], bl4[2], bl4[3]);
                MMA16816(s[nc2 * 2 + 1], ql[kc], bh4[2], bh4[3]);
            }
        }

        const bool diag = (kt == qt);
        const int mg0 = w * 16 + r0, mg1 = mg0 + 8;
#pragma unroll
        for (int nt = 0; nt < 8; nt++) {
#pragma unroll
            for (int c = 0; c < 4; c++) s[nt][c] *= scale;
            if (diag) {
                int n0 = nt * 8 + ncol;
                if (n0     > mg0) s[nt][0] = -1e30f;
                if (n0 + 1 > mg0) s[nt][1] = -1e30f;
                if (n0     > mg1) s[nt][2] = -1e30f;
                if (n0 + 1 > mg1) s[nt][3] = -1e30f;
            }
        }

        float mx0 = mrow0, mx1 = mrow1;
#pragma unroll
        for (int nt = 0; nt < 8; nt++) {
            mx0 = fmaxf(mx0, fmaxf(s[nt][0], s[nt][1]));
            mx1 = fmaxf(mx1, fmaxf(s[nt][2], s[nt][3]));
        }
        mx0 = fmaxf(mx0, __shfl_xor_sync(0xffffffffu, mx0, 1));
        mx0 = fmaxf(mx0, __shfl_xor_sync(0xffffffffu, mx0, 2));
        mx1 = fmaxf(mx1, __shfl_xor_sync(0xffffffffu, mx1, 1));
        mx1 = fmaxf(mx1, __shfl_xor_sync(0xffffffffu, mx1, 2));
        float a0 = __expf(mrow0 - mx0), a1 = __expf(mrow1 - mx1);
        mrow0 = mx0; mrow1 = mx1;
        float ps0 = 0.f, ps1 = 0.f;
#pragma unroll
        for (int nt = 0; nt < 8; nt++) {
            s[nt][0] = __expf(s[nt][0] - mx0);
            s[nt][1] = __expf(s[nt][1] - mx0);
            s[nt][2] = __expf(s[nt][2] - mx1);
            s[nt][3] = __expf(s[nt][3] - mx1);
            ps0 += s[nt][0] + s[nt][1];
            ps1 += s[nt][2] + s[nt][3];
        }
        ps0 += __shfl_xor_sync(0xffffffffu, ps0, 1);
        ps0 += __shfl_xor_sync(0xffffffffu, ps0, 2);
        ps1 += __shfl_xor_sync(0xffffffffu, ps1, 1);
        ps1 += __shfl_xor_sync(0xffffffffu, ps1, 2);
        lrow0 = lrow0 * a0 + ps0;
        lrow1 = lrow1 * a1 + ps1;
#pragma unroll
        for (int dn = 0; dn < 16; dn++) {
            O[dn][0] *= a0; O[dn][1] *= a0;
            O[dn][2] *= a1; O[dn][3] *= a1;
        }

#pragma unroll
        for (int pk = 0; pk < 4; pk++) {
            uint32_t ph[4], pl[4];
#pragma unroll
            for (int half = 0; half < 2; half++) {
                int nt = pk * 2 + half;
                __nv_bfloat16 h0 = __float2bfloat16(s[nt][0]);
                __nv_bfloat16 h1 = __float2bfloat16(s[nt][1]);
                __nv_bfloat16 h2 = __float2bfloat16(s[nt][2]);
                __nv_bfloat16 h3 = __float2bfloat16(s[nt][3]);
                ph[half * 2]     = b2(h0, h1);
                ph[half * 2 + 1] = b2(h2, h3);
                pl[half * 2]     = b2(__float2bfloat16(s[nt][0] - __bfloat162float(h0)),
                                      __float2bfloat16(s[nt][1] - __bfloat162float(h1)));
                pl[half * 2 + 1] = b2(__float2bfloat16(s[nt][2] - __bfloat162float(h2)),
                                      __float2bfloat16(s[nt][3] - __bfloat162float(h3)));
            }
            uint32_t pa_h[4] = {ph[0], ph[1], ph[2], ph[3]};
            uint32_t pa_l[4] = {pl[0], pl[1], pl[2], pl[3]};
#pragma unroll
            for (int dn2 = 0; dn2 < 8; dn2++) {
                uint32_t addr = VhS + (uint32_t)(pk * 16 + (lane & 15)) * PITB +
                                (uint32_t)((dn2 * 2 + (lane >> 4)) * 16);
                uint32_t vh4[4], vl4[4];
                LDM4T(vh4, addr);
                LDM4T(vl4, addr + KVTILE);
                MMA16816(O[dn2 * 2],     pa_h, vh4[0], vh4[1]);
                MMA16816(O[dn2 * 2],     pa_l, vh4[0], vh4[1]);
                MMA16816(O[dn2 * 2],     pa_h, vl4[0], vl4[1]);
                MMA16816(O[dn2 * 2 + 1], pa_h, vh4[2], vh4[3]);
                MMA16816(O[dn2 * 2 + 1], pa_l, vh4[2], vh4[3]);
                MMA16816(O[dn2 * 2 + 1], pa_h, vl4[2], vl4[3]);
            }
        }
        __syncthreads();
    }

    float il0 = 1.f / lrow0, il1 = 1.f / lrow1;
    const int m_glob0 = qt * 64 + w * 16 + r0;
    const int m_glob1 = m_glob0 + 8;
#pragma unroll
    for (int dn = 0; dn < 16; dn++) {
        int d = dn * 8 + ncol;
        *(float2*)&g_ctx[(tokbase + m_glob0) * HIDDEN + (size_t)h * HDIM + d] =
            make_float2(O[dn][0] * il0, O[dn][1] * il0);
        *(float2*)&g_ctx[(tokbase + m_glob1) * HIDDEN + (size_t)h * HDIM + d] =
            make_float2(O[dn][2] * il1, O[dn][3] * il1);
    }
}

/* ------------------------------------------------------------------ */
extern "C" void kernel_launch(void* const* d_in, const int* in_sizes, int n_in,
                              void* d_out, int out_size)
{
    (void)in_sizes; (void)n_in; (void)out_size;
    const float* hs   = (const float*)d_in[0];
    const int*   pos  = (const int*)  d_in[1];
    const float* Wqkv = (const float*)d_in[2];
    const float* bqkv = (const float*)d_in[3];
    const float* Wo   = (const float*)d_in[4];
    float* out = (float*)d_out;

    float *qkv, *ctx;
    __half *ahi, *alo, *bhq, *bho;
    cudaGetSymbolAddress((void**)&qkv, g_qkv);
    cudaGetSymbolAddress((void**)&ctx, g_ctx);
    cudaGetSymbolAddress((void**)&ahi, g_Ahi);
    cudaGetSymbolAddress((void**)&alo, g_Alo);
    cudaGetSymbolAddress((void**)&bhq, g_BhQ);
    cudaGetSymbolAddress((void**)&bho, g_BhO);

    cudaFuncSetAttribute(gemm_mma,
                         cudaFuncAttributeMaxDynamicSharedMemorySize, GEMM_SMEM);
    cudaFuncSetAttribute(flash_mma,
                         cudaFuncAttributeMaxDynamicSharedMemorySize, FLASH_SMEM);

    /* 1. pack inputs + weights */
    pack_a<<<dim3(KC, MT), 256>>>(hs, ahi, alo);
    pack_bt<<<dim3(NTQ, KC), 256>>>(Wqkv, QKVW, bhq);

    /* 2. QKV projection (+bias) */
    gemm_mma<<<dim3(NTQ, MT), 256, GEMM_SMEM>>>(ahi, alo, bhq, bqkv, qkv, QKVW);

    /* 3. RoPE */
    rope2<<<TOK, 128>>>(pos);

    /* 4. causal flash attention -> ctx */
    flash_mma<<<dim3(SSEQ / 64, NHEADS, BB), 128, FLASH_SMEM>>>();

    /* 5. O projection */
    pack_a<<<dim3(KC, MT), 256>>>(ctx, ahi, alo);
    pack_bt<<<dim3(NTO, KC), 256>>>(Wo, HIDDEN, bho);
    gemm_mma<<<dim3(NTO, MT), 256, GEMM_SMEM>>>(ahi, alo, bho, nullptr, out, HIDDEN);
}

// round 9
// speedup vs baseline: 7.9025x; 1.1242x over previous
#include <cuda_runtime.h>
#include <cuda_bf16.h>
#include <cuda_fp16.h>
#include <math.h>
#include <stdint.h>

#define HIDDEN 4096
#define NHEADS 32
#define HDIM   128
#define BB     2
#define SSEQ   2048
#define TOK    (BB * SSEQ)
#define QKVW   (3 * HIDDEN)

#define MT  (TOK / 128)
#define KC  (HIDDEN / 64)
#define NTQ (QKVW / 128)
#define NTO (HIDDEN / 128)
#define TILE_ELEMS 8192

/* ---------------- device scratch ---------------- */
__device__ float g_qkv[(size_t)TOK * QKVW];
__device__ float g_ctx[(size_t)TOK * HIDDEN];
__device__ __align__(1024) __half g_Ahi[(size_t)MT * KC * TILE_ELEMS];
__device__ __align__(1024) __half g_Alo[(size_t)MT * KC * TILE_ELEMS];
__device__ __align__(1024) __half g_BhQ[(size_t)NTQ * KC * TILE_ELEMS];
__device__ __align__(1024) __half g_BhO[(size_t)NTO * KC * TILE_ELEMS];

/* ---------------- helpers ---------------- */
__device__ __forceinline__ uint32_t smem_u32(const void* p) {
    uint32_t a;
    asm("{ .reg .u64 t; cvta.to.shared.u64 t, %1; cvt.u32.u64 %0, t; }"
        : "=r"(a) : "l"(p));
    return a;
}
__device__ __forceinline__ uint32_t sw128(uint32_t b) { return b ^ ((b >> 3) & 0x70); }

__device__ __forceinline__ void cp16(uint32_t d, const void* s) {
    asm volatile("cp.async.cg.shared.global [%0], [%1], 16;" :: "r"(d), "l"(s));
}
#define CP_COMMIT() asm volatile("cp.async.commit_group;" ::: "memory")
template <int N> __device__ __forceinline__ void cp_wait() {
    asm volatile("cp.async.wait_group %0;" :: "n"(N) : "memory");
}

#define LDM4(r, a)                                                            \
    asm volatile("ldmatrix.sync.aligned.m8n8.x4.shared.b16 {%0,%1,%2,%3}, [%4];" \
        : "=r"((r)[0]), "=r"((r)[1]), "=r"((r)[2]), "=r"((r)[3]) : "r"(a))
#define LDM4T(r, a)                                                           \
    asm volatile("ldmatrix.sync.aligned.m8n8.x4.trans.shared.b16 {%0,%1,%2,%3}, [%4];" \
        : "=r"((r)[0]), "=r"((r)[1]), "=r"((r)[2]), "=r"((r)[3]) : "r"(a))

/* fp16 HMMA */
#define MMAH16816(c, a, b0, b1)                                               \
    asm volatile("mma.sync.aligned.m16n8k16.row.col.f32.f16.f16.f32 "         \
        "{%0,%1,%2,%3}, {%4,%5,%6,%7}, {%8,%9}, {%0,%1,%2,%3};"               \
        : "+f"((c)[0]), "+f"((c)[1]), "+f"((c)[2]), "+f"((c)[3])              \
        : "r"((a)[0]), "r"((a)[1]), "r"((a)[2]), "r"((a)[3]), "r"(b0), "r"(b1))

__device__ __forceinline__ uint32_t h2(__half a, __half b) {
    __half2 t; t.x = a; t.y = b;
    return *(uint32_t*)&t;
}

/* ------------------------------------------------------------------ */
/* pack_a: fp32 -> swizzled fp16 hi/lo tile panels                     */
/* ------------------------------------------------------------------ */
__global__ __launch_bounds__(256) void pack_a(const float* __restrict__ A,
                                              __half* __restrict__ Oh,
                                              __half* __restrict__ Ol)
{
    const int kc = blockIdx.x, mt = blockIdx.y;
    char* oh = (char*)(Oh + ((size_t)mt * KC + kc) * TILE_ELEMS);
    char* ol = (char*)(Ol + ((size_t)mt * KC + kc) * TILE_ELEMS);
    for (int u = threadIdx.x; u < 1024; u += 256) {
        int r = u >> 3, c8 = (u & 7) * 8;
        const float* src = A + ((size_t)(mt * 128 + r)) * HIDDEN + kc * 64 + c8;
        float4 v0 = *(const float4*)src, v1 = *(const float4*)(src + 4);
        float v[8] = {v0.x, v0.y, v0.z, v0.w, v1.x, v1.y, v1.z, v1.w};
        __align__(16) __half h[8], l[8];
#pragma unroll
        for (int j = 0; j < 8; j++) {
            h[j] = __float2half_rn(v[j]);
            l[j] = __float2half_rn(v[j] - __half2float(h[j]));
        }
        uint32_t off = sw128((uint32_t)(r * 128 + c8 * 2));
        *(uint4*)(oh + off) = *(const uint4*)h;
        *(uint4*)(ol + off) = *(const uint4*)l;
    }
}

/* ------------------------------------------------------------------ */
/* pack_bt: W [K x N] fp32 -> transposed swizzled fp16 panel           */
/* ------------------------------------------------------------------ */
__global__ __launch_bounds__(256) void pack_bt(const float* __restrict__ W, int Ntot,
                                               __half* __restrict__ Oh)
{
    __shared__ float ts[64 * 129];
    const int nt = blockIdx.x, kc = blockIdx.y;
    for (int idx = threadIdx.x; idx < 64 * 128; idx += 256) {
        int k = idx >> 7, n = idx & 127;
        ts[k * 129 + n] = W[(size_t)(kc * 64 + k) * Ntot + nt * 128 + n];
    }
    __syncthreads();
    char* oh = (char*)(Oh + ((size_t)nt * KC + kc) * TILE_ELEMS);
    for (int u = threadIdx.x; u < 1024; u += 256) {
        int n = u >> 3, k8 = (u & 7) * 8;
        __align__(16) __half h[8];
#pragma unroll
        for (int j = 0; j < 8; j++)
            h[j] = __float2half_rn(ts[(k8 + j) * 129 + n]);
        uint32_t off = sw128((uint32_t)(n * 128 + k8 * 2));
        *(uint4*)(oh + off) = *(const uint4*)h;
    }
}

/* ------------------------------------------------------------------ */
/* fp16x2 mma GEMM (unchanged from round 6)                            */
/* ------------------------------------------------------------------ */
#define NSTG 2
#define STAGE_BYTES 49152
#define GEMM_SMEM (NSTG * STAGE_BYTES)

__global__ __launch_bounds__(256) void gemm_mma(
    const __half* __restrict__ Ah, const __half* __restrict__ Al,
    const __half* __restrict__ Bh,
    const float* __restrict__ bias, float* __restrict__ C, int Ntot)
{
    extern __shared__ char smem[];
    const uint32_t sb = smem_u32(smem);
    const int tid = threadIdx.x, wid = tid >> 5, lane = tid & 31;
    const int wm = wid & 1, wn = wid >> 1;
    const int nt = blockIdx.x, mt = blockIdx.y;

    const char* srcs[3] = {
        (const char*)(Ah + (size_t)mt * KC * TILE_ELEMS),
        (const char*)(Al + (size_t)mt * KC * TILE_ELEMS),
        (const char*)(Bh + (size_t)nt * KC * TILE_ELEMS)};

    float acc[4][4][4];
#pragma unroll
    for (int i = 0; i < 4; i++)
#pragma unroll
        for (int j = 0; j < 4; j++)
#pragma unroll
            for (int q = 0; q < 4; q++) acc[i][j][q] = 0.f;

    int rowA[4]; uint32_t offA[4];
#pragma unroll
    for (int mt2 = 0; mt2 < 4; mt2++) {
        rowA[mt2] = wm * 64 + mt2 * 16 + (lane & 15);
        offA[mt2] = (uint32_t)rowA[mt2] * 128;
    }
    const uint32_t cbA_base = (uint32_t)((lane >> 4) << 4);
    int rowB[2]; uint32_t offB[2];
#pragma unroll
    for (int np = 0; np < 2; np++) {
        rowB[np] = wn * 32 + np * 16 + ((lane & 7) | ((lane >> 4) << 3));
        offB[np] = (uint32_t)rowB[np] * 128;
    }
    const uint32_t cbB_base = (uint32_t)(((lane >> 3) & 1) << 4);

    auto copy_stage = [&](int j, int s) {
        size_t o = (size_t)j * 16384;
#pragma unroll
        for (int r = 0; r < 3; r++) {
            const char* src = srcs[r] + o + tid * 16;
            uint32_t dst = sb + s * STAGE_BYTES + r * 16384 + tid * 16;
#pragma unroll
            for (int it = 0; it < 4; it++)
                cp16(dst + it * 4096, src + (size_t)it * 4096);
        }
    };

    copy_stage(0, 0); CP_COMMIT();

    for (int i = 0; i < KC; i++) {
        int s = i & 1;
        if (i + 1 < KC) { copy_stage(i + 1, s ^ 1); CP_COMMIT(); cp_wait<1>(); }
        else            { cp_wait<0>(); }
        __syncthreads();

        const uint32_t aHi = sb + s * STAGE_BYTES;
        const uint32_t aLo = aHi + 16384;
        const uint32_t bHi = aHi + 32768;

#pragma unroll
        for (int ks = 0; ks < 4; ks++) {
            uint32_t ah[4][4], al[4][4];
#pragma unroll
            for (int mt2 = 0; mt2 < 4; mt2++) {
                uint32_t cb = (uint32_t)(ks * 32) + cbA_base;
                uint32_t off = offA[mt2] + (cb ^ (((uint32_t)rowA[mt2] & 7) << 4));
                LDM4(ah[mt2], aHi + off);
                LDM4(al[mt2], aLo + off);
            }
            uint32_t bh[4][2];
#pragma unroll
            for (int np = 0; np < 2; np++) {
                uint32_t cb = (uint32_t)(ks * 32) + cbB_base;
                uint32_t off = offB[np] + (cb ^ (((uint32_t)rowB[np] & 7) << 4));
                uint32_t t[4];
                LDM4(t, bHi + off);
                bh[np * 2][0] = t[0]; bh[np * 2][1] = t[1];
                bh[np * 2 + 1][0] = t[2]; bh[np * 2 + 1][1] = t[3];
            }
#pragma unroll
            for (int mt2 = 0; mt2 < 4; mt2++)
#pragma unroll
                for (int nt2 = 0; nt2 < 4; nt2++) {
                    MMAH16816(acc[mt2][nt2], ah[mt2], bh[nt2][0], bh[nt2][1]);
                    MMAH16816(acc[mt2][nt2], al[mt2], bh[nt2][0], bh[nt2][1]);
                }
        }
        __syncthreads();
    }

    const int r0 = mt * 128 + wm * 64 + (lane >> 2);
    const int c0 = nt * 128 + wn * 32 + (lane & 3) * 2;
#pragma unroll
    for (int mt2 = 0; mt2 < 4; mt2++) {
#pragma unroll
        for (int nt2 = 0; nt2 < 4; nt2++) {
            int row = r0 + mt2 * 16;
            int col = c0 + nt2 * 8;
            float b0 = 0.f, b1 = 0.f;
            if (bias) { b0 = bias[col]; b1 = bias[col + 1]; }
            float2* p0 = (float2*)&C[(size_t)row * Ntot + col];
            *p0 = make_float2(acc[mt2][nt2][0] + b0, acc[mt2][nt2][1] + b1);
            float2* p1 = (float2*)&C[(size_t)(row + 8) * Ntot + col];
            *p1 = make_float2(acc[mt2][nt2][2] + b0, acc[mt2][nt2][3] + b1);
        }
    }
}

/* ------------------------------------------------------------------ */
/* RoPE v2 (unchanged)                                                 */
/* ------------------------------------------------------------------ */
__global__ __launch_bounds__(128) void rope2(const int* __restrict__ positions)
{
    __shared__ float cs[64], sn[64];
    const int tok = blockIdx.x;
    if (threadIdx.x < 64) {
        int p = positions[tok];
        double inv = exp(-(double)threadIdx.x * (9.210340371976184 / 64.0));
        double a = (double)p * inv;
        cs[threadIdx.x] = (float)cos(a);
        sn[threadIdx.x] = (float)sin(a);
    }
    __syncthreads();
    const size_t base = (size_t)tok * QKVW;
    for (int i = threadIdx.x; i < NHEADS * 64; i += 128) {
        int h = i >> 6, d = i & 63;
        float c = cs[d], s = sn[d];
        size_t o = base + (size_t)h * HDIM + d;
        float x1 = g_qkv[o], x2 = g_qkv[o + 64];
        g_qkv[o]      = x1 * c - x2 * s;
        g_qkv[o + 64] = x2 * c + x1 * s;
        o += HIDDEN;
        x1 = g_qkv[o]; x2 = g_qkv[o + 64];
        g_qkv[o]      = x1 * c - x2 * s;
        g_qkv[o + 64] = x2 * c + x1 * s;
    }
}

/* ------------------------------------------------------------------ */
/* Flash attention, fp16x2: Q = Qh+Ql fp16 (regs), K,V single fp16.    */
/* S = Qh K + Ql K;  O += Ph V + Pl V.  fp32 accumulators.             */
/* smem: K | V tiles (17KB each). Q overlaps K/V during prologue.      */
/* ------------------------------------------------------------------ */
#define PITB   272
#define KVTILE 17408
#define FLASH_SMEM (2 * KVTILE)

__global__ __launch_bounds__(128) void flash_mma()
{
    extern __shared__ char sm[];
    const uint32_t sb = smem_u32(sm);
    const uint32_t KS = sb, VS = sb + KVTILE;
    const uint32_t QhS = sb, QlS = sb + KVTILE;   /* prologue only */

    const int tid = threadIdx.x, w = tid >> 5, lane = tid & 31;
    const int qt = blockIdx.x, h = blockIdx.y, b = blockIdx.z;
    const size_t tokbase = (size_t)b * SSEQ;
    const float scale = 0.08838834764831845f;

    /* ---- Q tile -> hi/lo fp16 smem ---- */
    for (int i = tid; i < 64 * 32; i += 128) {
        int r = i >> 5, c4 = i & 31;
        float4 v = *(const float4*)&g_qkv[(tokbase + qt * 64 + r) * QKVW +
                                          (size_t)h * HDIM + c4 * 4];
        __half hx = __float2half_rn(v.x), hy = __float2half_rn(v.y);
        __half hz = __float2half_rn(v.z), hw = __float2half_rn(v.w);
        *(uint2*)(sm + (QhS - sb) + r * PITB + c4 * 8) =
            make_uint2(h2(hx, hy), h2(hz, hw));
        *(uint2*)(sm + (QlS - sb) + r * PITB + c4 * 8) = make_uint2(
            h2(__float2half_rn(v.x - __half2float(hx)),
               __float2half_rn(v.y - __half2float(hy))),
            h2(__float2half_rn(v.z - __half2float(hz)),
               __float2half_rn(v.w - __half2float(hw))));
    }
    __syncthreads();

    /* ---- Q fragments to registers ---- */
    uint32_t qh[8][4], ql[8][4];
    {
        const int m0 = w * 16;
#pragma unroll
        for (int kc = 0; kc < 8; kc++) {
            uint32_t addr = QhS + (uint32_t)(m0 + (lane & 15)) * PITB +
                            (uint32_t)((kc * 2 + (lane >> 4)) * 16);
            LDM4(qh[kc], addr);
            LDM4(ql[kc], addr + KVTILE);
        }
    }
    __syncthreads();

    float O[16][4];
#pragma unroll
    for (int i = 0; i < 16; i++)
#pragma unroll
        for (int c = 0; c < 4; c++) O[i][c] = 0.f;
    float mrow0 = -INFINITY, mrow1 = -INFINITY, lrow0 = 0.f, lrow1 = 0.f;

    const int r0 = lane >> 2;
    const int ncol = (lane & 3) * 2;

    for (int kt = 0; kt <= qt; kt++) {
        /* ---- K,V tile -> fp16 smem ---- */
        for (int i = tid; i < 64 * 32; i += 128) {
            int r = i >> 5, c4 = i & 31;
            size_t rowb = (tokbase + kt * 64 + r) * QKVW + (size_t)h * HDIM + c4 * 4;
            float4 kv = *(const float4*)&g_qkv[rowb + HIDDEN];
            float4 vv = *(const float4*)&g_qkv[rowb + 2 * HIDDEN];
            uint32_t off = r * PITB + c4 * 8;
            *(uint2*)(sm + (KS - sb) + off) = make_uint2(
                h2(__float2half_rn(kv.x), __float2half_rn(kv.y)),
                h2(__float2half_rn(kv.z), __float2half_rn(kv.w)));
            *(uint2*)(sm + (VS - sb) + off) = make_uint2(
                h2(__float2half_rn(vv.x), __float2half_rn(vv.y)),
                h2(__float2half_rn(vv.z), __float2half_rn(vv.w)));
        }
        __syncthreads();

        /* ---- S = Q K^T ---- */
        float s[8][4];
#pragma unroll
        for (int i = 0; i < 8; i++)
#pragma unroll
            for (int c = 0; c < 4; c++) s[i][c] = 0.f;

#pragma unroll
        for (int kc = 0; kc < 8; kc++) {
#pragma unroll
            for (int nc2 = 0; nc2 < 4; nc2++) {
                int nrow = nc2 * 16 + ((lane >> 4) << 3) + (lane & 7);
                int col16 = kc * 2 + ((lane >> 3) & 1);
                uint32_t addr = KS + (uint32_t)nrow * PITB + (uint32_t)col16 * 16;
                uint32_t k4[4];
                LDM4(k4, addr);
                MMAH16816(s[nc2 * 2],     qh[kc], k4[0], k4[1]);
                MMAH16816(s[nc2 * 2],     ql[kc], k4[0], k4[1]);
                MMAH16816(s[nc2 * 2 + 1], qh[kc], k4[2], k4[3]);
                MMAH16816(s[nc2 * 2 + 1], ql[kc], k4[2], k4[3]);
            }
        }

        /* ---- scale + causal mask ---- */
        const bool diag = (kt == qt);
        const int mg0 = w * 16 + r0, mg1 = mg0 + 8;
#pragma unroll
        for (int nt = 0; nt < 8; nt++) {
#pragma unroll
            for (int c = 0; c < 4; c++) s[nt][c] *= scale;
            if (diag) {
                int n0 = nt * 8 + ncol;
                if (n0     > mg0) s[nt][0] = -1e30f;
                if (n0 + 1 > mg0) s[nt][1] = -1e30f;
                if (n0     > mg1) s[nt][2] = -1e30f;
                if (n0 + 1 > mg1) s[nt][3] = -1e30f;
            }
        }

        /* ---- online softmax ---- */
        float mx0 = mrow0, mx1 = mrow1;
#pragma unroll
        for (int nt = 0; nt < 8; nt++) {
            mx0 = fmaxf(mx0, fmaxf(s[nt][0], s[nt][1]));
            mx1 = fmaxf(mx1, fmaxf(s[nt][2], s[nt][3]));
        }
        mx0 = fmaxf(mx0, __shfl_xor_sync(0xffffffffu, mx0, 1));
        mx0 = fmaxf(mx0, __shfl_xor_sync(0xffffffffu, mx0, 2));
        mx1 = fmaxf(mx1, __shfl_xor_sync(0xffffffffu, mx1, 1));
        mx1 = fmaxf(mx1, __shfl_xor_sync(0xffffffffu, mx1, 2));
        float a0 = __expf(mrow0 - mx0), a1 = __expf(mrow1 - mx1);
        mrow0 = mx0; mrow1 = mx1;
        float ps0 = 0.f, ps1 = 0.f;
#pragma unroll
        for (int nt = 0; nt < 8; nt++) {
            s[nt][0] = __expf(s[nt][0] - mx0);
            s[nt][1] = __expf(s[nt][1] - mx0);
            s[nt][2] = __expf(s[nt][2] - mx1);
            s[nt][3] = __expf(s[nt][3] - mx1);
            ps0 += s[nt][0] + s[nt][1];
            ps1 += s[nt][2] + s[nt][3];
        }
        ps0 += __shfl_xor_sync(0xffffffffu, ps0, 1);
        ps0 += __shfl_xor_sync(0xffffffffu, ps0, 2);
        ps1 += __shfl_xor_sync(0xffffffffu, ps1, 1);
        ps1 += __shfl_xor_sync(0xffffffffu, ps1, 2);
        lrow0 = lrow0 * a0 + ps0;
        lrow1 = lrow1 * a1 + ps1;
#pragma unroll
        for (int dn = 0; dn < 16; dn++) {
            O[dn][0] *= a0; O[dn][1] *= a0;
            O[dn][2] *= a1; O[dn][3] *= a1;
        }

        /* ---- O += P V (P = Ph + Pl fp16) ---- */
#pragma unroll
        for (int pk = 0; pk < 4; pk++) {
            uint32_t pa_h[4], pa_l[4];
#pragma unroll
            for (int half = 0; half < 2; half++) {
                int nt = pk * 2 + half;
                __half h0 = __float2half_rn(s[nt][0]);
                __half h1 = __float2half_rn(s[nt][1]);
                __half h2_ = __float2half_rn(s[nt][2]);
                __half h3 = __float2half_rn(s[nt][3]);
                pa_h[half * 2]     = h2(h0, h1);
                pa_h[half * 2 + 1] = h2(h2_, h3);
                pa_l[half * 2]     = h2(__float2half_rn(s[nt][0] - __half2float(h0)),
                                        __float2half_rn(s[nt][1] - __half2float(h1)));
                pa_l[half * 2 + 1] = h2(__float2half_rn(s[nt][2] - __half2float(h2_)),
                                        __float2half_rn(s[nt][3] - __half2float(h3)));
            }
#pragma unroll
            for (int dn2 = 0; dn2 < 8; dn2++) {
                uint32_t addr = VS + (uint32_t)(pk * 16 + (lane & 15)) * PITB +
                                (uint32_t)((dn2 * 2 + (lane >> 4)) * 16);
                uint32_t v4[4];
                LDM4T(v4, addr);
                MMAH16816(O[dn2 * 2],     pa_h, v4[0], v4[1]);
                MMAH16816(O[dn2 * 2],     pa_l, v4[0], v4[1]);
                MMAH16816(O[dn2 * 2 + 1], pa_h, v4[2], v4[3]);
                MMAH16816(O[dn2 * 2 + 1], pa_l, v4[2], v4[3]);
            }
        }
        __syncthreads();
    }

    /* ---- epilogue ---- */
    float il0 = 1.f / lrow0, il1 = 1.f / lrow1;
    const int m_glob0 = qt * 64 + w * 16 + r0;
    const int m_glob1 = m_glob0 + 8;
#pragma unroll
    for (int dn = 0; dn < 16; dn++) {
        int d = dn * 8 + ncol;
        *(float2*)&g_ctx[(tokbase + m_glob0) * HIDDEN + (size_t)h * HDIM + d] =
            make_float2(O[dn][0] * il0, O[dn][1] * il0);
        *(float2*)&g_ctx[(tokbase + m_glob1) * HIDDEN + (size_t)h * HDIM + d] =
            make_float2(O[dn][2] * il1, O[dn][3] * il1);
    }
}

/* ------------------------------------------------------------------ */
extern "C" void kernel_launch(void* const* d_in, const int* in_sizes, int n_in,
                              void* d_out, int out_size)
{
    (void)in_sizes; (void)n_in; (void)out_size;
    const float* hs   = (const float*)d_in[0];
    const int*   pos  = (const int*)  d_in[1];
    const float* Wqkv = (const float*)d_in[2];
    const float* bqkv = (const float*)d_in[3];
    const float* Wo   = (const float*)d_in[4];
    float* out = (float*)d_out;

    float *qkv, *ctx;
    __half *ahi, *alo, *bhq, *bho;
    cudaGetSymbolAddress((void**)&qkv, g_qkv);
    cudaGetSymbolAddress((void**)&ctx, g_ctx);
    cudaGetSymbolAddress((void**)&ahi, g_Ahi);
    cudaGetSymbolAddress((void**)&alo, g_Alo);
    cudaGetSymbolAddress((void**)&bhq, g_BhQ);
    cudaGetSymbolAddress((void**)&bho, g_BhO);

    cudaFuncSetAttribute(gemm_mma,
                         cudaFuncAttributeMaxDynamicSharedMemorySize, GEMM_SMEM);
    cudaFuncSetAttribute(flash_mma,
                         cudaFuncAttributeMaxDynamicSharedMemorySize, FLASH_SMEM);

    /* 1. pack inputs + weights */
    pack_a<<<dim3(KC, MT), 256>>>(hs, ahi, alo);
    pack_bt<<<dim3(NTQ, KC), 256>>>(Wqkv, QKVW, bhq);

    /* 2. QKV projection (+bias) */
    gemm_mma<<<dim3(NTQ, MT), 256, GEMM_SMEM>>>(ahi, alo, bhq, bqkv, qkv, QKVW);

    /* 3. RoPE */
    rope2<<<TOK, 128>>>(pos);

    /* 4. causal flash attention -> ctx */
    flash_mma<<<dim3(SSEQ / 64, NHEADS, BB), 128, FLASH_SMEM>>>();

    /* 5. O projection */
    pack_a<<<dim3(KC, MT), 256>>>(ctx, ahi, alo);
    pack_bt<<<dim3(NTO, KC), 256>>>(Wo, HIDDEN, bho);
    gemm_mma<<<dim3(NTO, MT), 256, GEMM_SMEM>>>(ahi, alo, bho, nullptr, out, HIDDEN);
}

// round 13
// speedup vs baseline: 8.1656x; 1.0333x over previous
#include <cuda_runtime.h>
#include <cuda_fp16.h>
#include <math.h>
#include <stdint.h>

#define HIDDEN 4096
#define NHEADS 32
#define HDIM   128
#define BB     2
#define SSEQ   2048
#define TOK    (BB * SSEQ)
#define QKVW   (3 * HIDDEN)

#define MT  (TOK / 128)
#define KC  (HIDDEN / 64)
#define NTQ (QKVW / 128)
#define NTO (HIDDEN / 128)
#define TILE_ELEMS 8192

/* ---------------- device scratch ---------------- */
__device__ float g_qkv[(size_t)TOK * QKVW];
__device__ float g_ctx[(size_t)TOK * HIDDEN];
__device__ __align__(1024) __half g_Ahi[(size_t)MT * KC * TILE_ELEMS];
__device__ __align__(1024) __half g_Alo[(size_t)MT * KC * TILE_ELEMS];
__device__ __align__(1024) __half g_BhQ[(size_t)NTQ * KC * TILE_ELEMS];
__device__ __align__(1024) __half g_BhO[(size_t)NTO * KC * TILE_ELEMS];
__device__ __align__(256)  __half g_k16[(size_t)BB * NHEADS * SSEQ * HDIM];
__device__ __align__(256)  __half g_v16[(size_t)BB * NHEADS * SSEQ * HDIM];

/* ---------------- helpers ---------------- */
__device__ __forceinline__ uint32_t smem_u32(const void* p) {
    uint32_t a;
    asm("{ .reg .u64 t; cvta.to.shared.u64 t, %1; cvt.u32.u64 %0, t; }"
        : "=r"(a) : "l"(p));
    return a;
}
__device__ __forceinline__ uint32_t sw128(uint32_t b) { return b ^ ((b >> 3) & 0x70); }

__device__ __forceinline__ void cp16(uint32_t d, const void* s) {
    asm volatile("cp.async.cg.shared.global [%0], [%1], 16;" :: "r"(d), "l"(s));
}
#define CP_COMMIT() asm volatile("cp.async.commit_group;" ::: "memory")
template <int N> __device__ __forceinline__ void cp_wait() {
    asm volatile("cp.async.wait_group %0;" :: "n"(N) : "memory");
}

#define LDM4(r, a)                                                            \
    asm volatile("ldmatrix.sync.aligned.m8n8.x4.shared.b16 {%0,%1,%2,%3}, [%4];" \
        : "=r"((r)[0]), "=r"((r)[1]), "=r"((r)[2]), "=r"((r)[3]) : "r"(a))
#define LDM4T(r, a)                                                           \
    asm volatile("ldmatrix.sync.aligned.m8n8.x4.trans.shared.b16 {%0,%1,%2,%3}, [%4];" \
        : "=r"((r)[0]), "=r"((r)[1]), "=r"((r)[2]), "=r"((r)[3]) : "r"(a))

#define MMAH16816(c, a, b0, b1)                                               \
    asm volatile("mma.sync.aligned.m16n8k16.row.col.f32.f16.f16.f32 "         \
        "{%0,%1,%2,%3}, {%4,%5,%6,%7}, {%8,%9}, {%0,%1,%2,%3};"               \
        : "+f"((c)[0]), "+f"((c)[1]), "+f"((c)[2]), "+f"((c)[3])              \
        : "r"((a)[0]), "r"((a)[1]), "r"((a)[2]), "r"((a)[3]), "r"(b0), "r"(b1))

__device__ __forceinline__ uint32_t h2(__half a, __half b) {
    __half2 t; t.x = a; t.y = b;
    return *(uint32_t*)&t;
}

/* ------------------------------------------------------------------ */
/* pack_a: fp32 -> swizzled fp16 hi/lo tile panels                     */
/* ------------------------------------------------------------------ */
__global__ __launch_bounds__(256) void pack_a(const float* __restrict__ A,
                                              __half* __restrict__ Oh,
                                              __half* __restrict__ Ol)
{
    const int kc = blockIdx.x, mt = blockIdx.y;
    char* oh = (char*)(Oh + ((size_t)mt * KC + kc) * TILE_ELEMS);
    char* ol = (char*)(Ol + ((size_t)mt * KC + kc) * TILE_ELEMS);
    for (int u = threadIdx.x; u < 1024; u += 256) {
        int r = u >> 3, c8 = (u & 7) * 8;
        const float* src = A + ((size_t)(mt * 128 + r)) * HIDDEN + kc * 64 + c8;
        float4 v0 = *(const float4*)src, v1 = *(const float4*)(src + 4);
        float v[8] = {v0.x, v0.y, v0.z, v0.w, v1.x, v1.y, v1.z, v1.w};
        __align__(16) __half h[8], l[8];
#pragma unroll
        for (int j = 0; j < 8; j++) {
            h[j] = __float2half_rn(v[j]);
            l[j] = __float2half_rn(v[j] - __half2float(h[j]));
        }
        uint32_t off = sw128((uint32_t)(r * 128 + c8 * 2));
        *(uint4*)(oh + off) = *(const uint4*)h;
        *(uint4*)(ol + off) = *(const uint4*)l;
    }
}

/* ------------------------------------------------------------------ */
/* pack_bt: W [K x N] fp32 -> transposed swizzled fp16 panel           */
/* ------------------------------------------------------------------ */
__global__ __launch_bounds__(256) void pack_bt(const float* __restrict__ W, int Ntot,
                                               __half* __restrict__ Oh)
{
    __shared__ float ts[64 * 129];
    const int nt = blockIdx.x, kc = blockIdx.y;
    for (int idx = threadIdx.x; idx < 64 * 128; idx += 256) {
        int k = idx >> 7, n = idx & 127;
        ts[k * 129 + n] = W[(size_t)(kc * 64 + k) * Ntot + nt * 128 + n];
    }
    __syncthreads();
    char* oh = (char*)(Oh + ((size_t)nt * KC + kc) * TILE_ELEMS);
    for (int u = threadIdx.x; u < 1024; u += 256) {
        int n = u >> 3, k8 = (u & 7) * 8;
        __align__(16) __half h[8];
#pragma unroll
        for (int j = 0; j < 8; j++)
            h[j] = __float2half_rn(ts[(k8 + j) * 129 + n]);
        uint32_t off = sw128((uint32_t)(n * 128 + k8 * 2));
        *(uint4*)(oh + off) = *(const uint4*)h;
    }
}

/* ------------------------------------------------------------------ */
/* fp16x2 mma GEMM (unchanged)                                         */
/* ------------------------------------------------------------------ */
#define NSTG 2
#define STAGE_BYTES 49152
#define GEMM_SMEM (NSTG * STAGE_BYTES)

__global__ __launch_bounds__(256) void gemm_mma(
    const __half* __restrict__ Ah, const __half* __restrict__ Al,
    const __half* __restrict__ Bh,
    const float* __restrict__ bias, float* __restrict__ C, int Ntot)
{
    extern __shared__ char smem[];
    const uint32_t sb = smem_u32(smem);
    const int tid = threadIdx.x, wid = tid >> 5, lane = tid & 31;
    const int wm = wid & 1, wn = wid >> 1;
    const int nt = blockIdx.x, mt = blockIdx.y;

    const char* srcs[3] = {
        (const char*)(Ah + (size_t)mt * KC * TILE_ELEMS),
        (const char*)(Al + (size_t)mt * KC * TILE_ELEMS),
        (const char*)(Bh + (size_t)nt * KC * TILE_ELEMS)};

    float acc[4][4][4];
#pragma unroll
    for (int i = 0; i < 4; i++)
#pragma unroll
        for (int j = 0; j < 4; j++)
#pragma unroll
            for (int q = 0; q < 4; q++) acc[i][j][q] = 0.f;

    int rowA[4]; uint32_t offA[4];
#pragma unroll
    for (int mt2 = 0; mt2 < 4; mt2++) {
        rowA[mt2] = wm * 64 + mt2 * 16 + (lane & 15);
        offA[mt2] = (uint32_t)rowA[mt2] * 128;
    }
    const uint32_t cbA_base = (uint32_t)((lane >> 4) << 4);
    int rowB[2]; uint32_t offB[2];
#pragma unroll
    for (int np = 0; np < 2; np++) {
        rowB[np] = wn * 32 + np * 16 + ((lane & 7) | ((lane >> 4) << 3));
        offB[np] = (uint32_t)rowB[np] * 128;
    }
    const uint32_t cbB_base = (uint32_t)(((lane >> 3) & 1) << 4);

    auto copy_stage = [&](int j, int s) {
        size_t o = (size_t)j * 16384;
#pragma unroll
        for (int r = 0; r < 3; r++) {
            const char* src = srcs[r] + o + tid * 16;
            uint32_t dst = sb + s * STAGE_BYTES + r * 16384 + tid * 16;
#pragma unroll
            for (int it = 0; it < 4; it++)
                cp16(dst + it * 4096, src + (size_t)it * 4096);
        }
    };

    copy_stage(0, 0); CP_COMMIT();

    for (int i = 0; i < KC; i++) {
        int s = i & 1;
        if (i + 1 < KC) { copy_stage(i + 1, s ^ 1); CP_COMMIT(); cp_wait<1>(); }
        else            { cp_wait<0>(); }
        __syncthreads();

        const uint32_t aHi = sb + s * STAGE_BYTES;
        const uint32_t aLo = aHi + 16384;
        const uint32_t bHi = aHi + 32768;

#pragma unroll
        for (int ks = 0; ks < 4; ks++) {
            uint32_t ah[4][4], al[4][4];
#pragma unroll
            for (int mt2 = 0; mt2 < 4; mt2++) {
                uint32_t cb = (uint32_t)(ks * 32) + cbA_base;
                uint32_t off = offA[mt2] + (cb ^ (((uint32_t)rowA[mt2] & 7) << 4));
                LDM4(ah[mt2], aHi + off);
                LDM4(al[mt2], aLo + off);
            }
            uint32_t bh[4][2];
#pragma unroll
            for (int np = 0; np < 2; np++) {
                uint32_t cb = (uint32_t)(ks * 32) + cbB_base;
                uint32_t off = offB[np] + (cb ^ (((uint32_t)rowB[np] & 7) << 4));
                uint32_t t[4];
                LDM4(t, bHi + off);
                bh[np * 2][0] = t[0]; bh[np * 2][1] = t[1];
                bh[np * 2 + 1][0] = t[2]; bh[np * 2 + 1][1] = t[3];
            }
#pragma unroll
            for (int mt2 = 0; mt2 < 4; mt2++)
#pragma unroll
                for (int nt2 = 0; nt2 < 4; nt2++) {
                    MMAH16816(acc[mt2][nt2], ah[mt2], bh[nt2][0], bh[nt2][1]);
                    MMAH16816(acc[mt2][nt2], al[mt2], bh[nt2][0], bh[nt2][1]);
                }
        }
        __syncthreads();
    }

    const int r0 = mt * 128 + wm * 64 + (lane >> 2);
    const int c0 = nt * 128 + wn * 32 + (lane & 3) * 2;
#pragma unroll
    for (int mt2 = 0; mt2 < 4; mt2++) {
#pragma unroll
        for (int nt2 = 0; nt2 < 4; nt2++) {
            int row = r0 + mt2 * 16;
            int col = c0 + nt2 * 8;
            float b0 = 0.f, b1 = 0.f;
            if (bias) { b0 = bias[col]; b1 = bias[col + 1]; }
            float2* p0 = (float2*)&C[(size_t)row * Ntot + col];
            *p0 = make_float2(acc[mt2][nt2][0] + b0, acc[mt2][nt2][1] + b1);
            float2* p1 = (float2*)&C[(size_t)(row + 8) * Ntot + col];
            *p1 = make_float2(acc[mt2][nt2][2] + b0, acc[mt2][nt2][3] + b1);
        }
    }
}

/* ------------------------------------------------------------------ */
/* rope3: rope q in place (fp32); rope k -> g_k16 fp16 [b][h][s][d];   */
/* copy v -> g_v16 fp16.                                               */
/* ------------------------------------------------------------------ */
__global__ __launch_bounds__(128) void rope3(const int* __restrict__ positions)
{
    __shared__ float cs[64], sn[64];
    const int tok = blockIdx.x;
    const int b = tok >> 11, s = tok & (SSEQ - 1);
    if (threadIdx.x < 64) {
        int p = positions[tok];
        double inv = exp(-(double)threadIdx.x * (9.210340371976184 / 64.0));
        double a = (double)p * inv;
        cs[threadIdx.x] = (float)cos(a);
        sn[threadIdx.x] = (float)sin(a);
    }
    __syncthreads();
    const size_t base = (size_t)tok * QKVW;
    for (int i = threadIdx.x; i < NHEADS * 64; i += 128) {
        int h = i >> 6, d = i & 63;
        float c = cs[d], sv = sn[d];
        size_t o = base + (size_t)h * HDIM + d;
        float x1 = g_qkv[o], x2 = g_qkv[o + 64];
        g_qkv[o]      = x1 * c - x2 * sv;
        g_qkv[o + 64] = x2 * c + x1 * sv;
        size_t ko = o + HIDDEN;
        x1 = g_qkv[ko]; x2 = g_qkv[ko + 64];
        size_t kb = ((size_t)(b * NHEADS + h) * SSEQ + s) * HDIM;
        g_k16[kb + d]      = __float2half_rn(x1 * c - x2 * sv);
        g_k16[kb + d + 64] = __float2half_rn(x2 * c + x1 * sv);
    }
    for (int i = threadIdx.x; i < HIDDEN / 4; i += 128) {
        float4 v = *(const float4*)&g_qkv[base + 2 * HIDDEN + (size_t)i * 4];
        int h = (i * 4) >> 7, d = (i * 4) & 127;
        size_t vb = ((size_t)(b * NHEADS + h) * SSEQ + s) * HDIM + d;
        *(uint2*)&g_v16[vb] = make_uint2(
            h2(__float2half_rn(v.x), __float2half_rn(v.y)),
            h2(__float2half_rn(v.z), __float2half_rn(v.w)));
    }
}

/* ------------------------------------------------------------------ */
/* Flash v2: BQ=128, 256 threads (8 warps x 16 rows).                  */
/* Q = Qh+Ql fp16 (regs) from fp32; K,V fp16 from g_k16/g_v16 via      */
/* double-buffered cp.async (2 x 34KB stages).                         */
/* ------------------------------------------------------------------ */
#define PITB   272
#define KVHALF 17408              /* 64 rows * 272 */
#define KVSTG  (2 * KVHALF)       /* K + V per stage */
#define FLASH_SMEM (2 * KVSTG)    /* 69632; Q prologue reuses it */

__global__ __launch_bounds__(256) void flash_mma()
{
    extern __shared__ char sm[];
    const uint32_t sb = smem_u32(sm);
    const uint32_t QhS = sb, QlS = sb + 34816;   /* prologue only */

    const int tid = threadIdx.x, w = tid >> 5, lane = tid & 31;
    const int qt = blockIdx.x, h = blockIdx.y, b = blockIdx.z;
    const size_t tokbase = (size_t)b * SSEQ;
    const size_t kvhead = (size_t)(b * NHEADS + h) * SSEQ;
    const float scale = 0.08838834764831845f;

    /* ---- Q tile (128 rows) -> hi/lo fp16 smem ---- */
    for (int i = tid; i < 128 * 32; i += 256) {
        int r = i >> 5, c4 = i & 31;
        float4 v = *(const float4*)&g_qkv[(tokbase + qt * 128 + r) * QKVW +
                                          (size_t)h * HDIM + c4 * 4];
        __half hx = __float2half_rn(v.x), hy = __float2half_rn(v.y);
        __half hz = __float2half_rn(v.z), hw = __float2half_rn(v.w);
        *(uint2*)(sm + r * PITB + c4 * 8) = make_uint2(h2(hx, hy), h2(hz, hw));
        *(uint2*)(sm + 34816 + r * PITB + c4 * 8) = make_uint2(
            h2(__float2half_rn(v.x - __half2float(hx)),
               __float2half_rn(v.y - __half2float(hy))),
            h2(__float2half_rn(v.z - __half2float(hz)),
               __float2half_rn(v.w - __half2float(hw))));
    }
    __syncthreads();

    /* ---- Q fragments to registers (per warp: rows w*16..+15) ---- */
    uint32_t qh[8][4], ql[8][4];
#pragma unroll
    for (int kc = 0; kc < 8; kc++) {
        uint32_t addr = QhS + (uint32_t)(w * 16 + (lane & 15)) * PITB +
                        (uint32_t)((kc * 2 + (lane >> 4)) * 16);
        LDM4(qh[kc], addr);
        LDM4(ql[kc], addr + 34816);
    }
    __syncthreads();

    float O[16][4];
#pragma unroll
    for (int i = 0; i < 16; i++)
#pragma unroll
        for (int c = 0; c < 4; c++) O[i][c] = 0.f;
    float mrow0 = -INFINITY, mrow1 = -INFINITY, lrow0 = 0.f, lrow1 = 0.f;

    const int r0 = lane >> 2;
    const int ncol = (lane & 3) * 2;
    const int mg0 = qt * 128 + w * 16 + r0, mg1 = mg0 + 8;

    auto load_kv = [&](int kt, int stg) {
        const char* kb = (const char*)(g_k16 + (kvhead + kt * 64) * HDIM);
        const char* vb = (const char*)(g_v16 + (kvhead + kt * 64) * HDIM);
        uint32_t ks = sb + stg * KVSTG, vs = ks + KVHALF;
        for (int i = tid; i < 1024; i += 256) {
            int r = i >> 4, c = i & 15;
            cp16(ks + r * PITB + c * 16, kb + r * 256 + c * 16);
            cp16(vs + r * PITB + c * 16, vb + r * 256 + c * 16);
        }
    };

    const int ktmax = 2 * qt + 1;
    load_kv(0, 0); CP_COMMIT();

    for (int kt = 0; kt <= ktmax; kt++) {
        int stg = kt & 1;
        if (kt < ktmax) { load_kv(kt + 1, stg ^ 1); CP_COMMIT(); cp_wait<1>(); }
        else            { cp_wait<0>(); }
        __syncthreads();

        /* warps entirely above the diagonal skip compute */
        if (kt * 64 <= qt * 128 + w * 16 + 15) {
            const uint32_t KS = sb + stg * KVSTG, VS = KS + KVHALF;

            float s[8][4];
#pragma unroll
            for (int i = 0; i < 8; i++)
#pragma unroll
                for (int c = 0; c < 4; c++) s[i][c] = 0.f;

#pragma unroll
            for (int kc = 0; kc < 8; kc++) {
#pragma unroll
                for (int nc2 = 0; nc2 < 4; nc2++) {
                    int nrow = nc2 * 16 + ((lane >> 4) << 3) + (lane & 7);
                    int col16 = kc * 2 + ((lane >> 3) & 1);
                    uint32_t addr = KS + (uint32_t)nrow * PITB + (uint32_t)col16 * 16;
                    uint32_t k4[4];
                    LDM4(k4, addr);
                    MMAH16816(s[nc2 * 2],     qh[kc], k4[0], k4[1]);
                    MMAH16816(s[nc2 * 2],     ql[kc], k4[0], k4[1]);
                    MMAH16816(s[nc2 * 2 + 1], qh[kc], k4[2], k4[3]);
                    MMAH16816(s[nc2 * 2 + 1], ql[kc], k4[2], k4[3]);
                }
            }

            /* scale + causal mask (only tiles crossing the diagonal) */
            const bool crossing = (kt >= 2 * qt);
#pragma unroll
            for (int nt = 0; nt < 8; nt++) {
#pragma unroll
                for (int c = 0; c < 4; c++) s[nt][c] *= scale;
                if (crossing) {
                    int n0 = kt * 64 + nt * 8 + ncol;
                    if (n0     > mg0) s[nt][0] = -1e30f;
                    if (n0 + 1 > mg0) s[nt][1] = -1e30f;
                    if (n0     > mg1) s[nt][2] = -1e30f;
                    if (n0 + 1 > mg1) s[nt][3] = -1e30f;
                }
            }

            /* online softmax */
            float mx0 = mrow0, mx1 = mrow1;
#pragma unroll
            for (int nt = 0; nt < 8; nt++) {
                mx0 = fmaxf(mx0, fmaxf(s[nt][0], s[nt][1]));
                mx1 = fmaxf(mx1, fmaxf(s[nt][2], s[nt][3]));
            }
            mx0 = fmaxf(mx0, __shfl_xor_sync(0xffffffffu, mx0, 1));
            mx0 = fmaxf(mx0, __shfl_xor_sync(0xffffffffu, mx0, 2));
            mx1 = fmaxf(mx1, __shfl_xor_sync(0xffffffffu, mx1, 1));
            mx1 = fmaxf(mx1, __shfl_xor_sync(0xffffffffu, mx1, 2));
            float a0 = __expf(mrow0 - mx0), a1 = __expf(mrow1 - mx1);
            mrow0 = mx0; mrow1 = mx1;
            float ps0 = 0.f, ps1 = 0.f;
#pragma unroll
            for (int nt = 0; nt < 8; nt++) {
                s[nt][0] = __expf(s[nt][0] - mx0);
                s[nt][1] = __expf(s[nt][1] - mx0);
                s[nt][2] = __expf(s[nt][2] - mx1);
                s[nt][3] = __expf(s[nt][3] - mx1);
                ps0 += s[nt][0] + s[nt][1];
                ps1 += s[nt][2] + s[nt][3];
            }
            ps0 += __shfl_xor_sync(0xffffffffu, ps0, 1);
            ps0 += __shfl_xor_sync(0xffffffffu, ps0, 2);
            ps1 += __shfl_xor_sync(0xffffffffu, ps1, 1);
            ps1 += __shfl_xor_sync(0xffffffffu, ps1, 2);
            lrow0 = lrow0 * a0 + ps0;
            lrow1 = lrow1 * a1 + ps1;
#pragma unroll
            for (int dn = 0; dn < 16; dn++) {
                O[dn][0] *= a0; O[dn][1] *= a0;
                O[dn][2] *= a1; O[dn][3] *= a1;
            }

            /* O += P V (P = Ph + Pl fp16) */
#pragma unroll
            for (int pk = 0; pk < 4; pk++) {
                uint32_t pa_h[4], pa_l[4];
#pragma unroll
                for (int half = 0; half < 2; half++) {
                    int nt = pk * 2 + half;
                    __half h0 = __float2half_rn(s[nt][0]);
                    __half h1 = __float2half_rn(s[nt][1]);
                    __half h2_ = __float2half_rn(s[nt][2]);
                    __half h3 = __float2half_rn(s[nt][3]);
                    pa_h[half * 2]     = h2(h0, h1);
                    pa_h[half * 2 + 1] = h2(h2_, h3);
                    pa_l[half * 2]     = h2(__float2half_rn(s[nt][0] - __half2float(h0)),
                                            __float2half_rn(s[nt][1] - __half2float(h1)));
                    pa_l[half * 2 + 1] = h2(__float2half_rn(s[nt][2] - __half2float(h2_)),
                                            __float2half_rn(s[nt][3] - __half2float(h3)));
                }
#pragma unroll
                for (int dn2 = 0; dn2 < 8; dn2++) {
                    uint32_t addr = VS + (uint32_t)(pk * 16 + (lane & 15)) * PITB +
                                    (uint32_t)((dn2 * 2 + (lane >> 4)) * 16);
                    uint32_t v4[4];
                    LDM4T(v4, addr);
                    MMAH16816(O[dn2 * 2],     pa_h, v4[0], v4[1]);
                    MMAH16816(O[dn2 * 2],     pa_l, v4[0], v4[1]);
                    MMAH16816(O[dn2 * 2 + 1], pa_h, v4[2], v4[3]);
                    MMAH16816(O[dn2 * 2 + 1], pa_l, v4[2], v4[3]);
                }
            }
        }
        __syncthreads();
    }

    /* ---- epilogue ---- */
    float il0 = 1.f / lrow0, il1 = 1.f / lrow1;
    const int m_glob0 = qt * 128 + w * 16 + r0;
    const int m_glob1 = m_glob0 + 8;
#pragma unroll
    for (int dn = 0; dn < 16; dn++) {
        int d = dn * 8 + ncol;
        *(float2*)&g_ctx[(tokbase + m_glob0) * HIDDEN + (size_t)h * HDIM + d] =
            make_float2(O[dn][0] * il0, O[dn][1] * il0);
        *(float2*)&g_ctx[(tokbase + m_glob1) * HIDDEN + (size_t)h * HDIM + d] =
            make_float2(O[dn][2] * il1, O[dn][3] * il1);
    }
}

/* ------------------------------------------------------------------ */
extern "C" void kernel_launch(void* const* d_in, const int* in_sizes, int n_in,
                              void* d_out, int out_size)
{
    (void)in_sizes; (void)n_in; (void)out_size;
    const float* hs   = (const float*)d_in[0];
    const int*   pos  = (const int*)  d_in[1];
    const float* Wqkv = (const float*)d_in[2];
    const float* bqkv = (const float*)d_in[3];
    const float* Wo   = (const float*)d_in[4];
    float* out = (float*)d_out;

    float *qkv, *ctx;
    __half *ahi, *alo, *bhq, *bho;
    cudaGetSymbolAddress((void**)&qkv, g_qkv);
    cudaGetSymbolAddress((void**)&ctx, g_ctx);
    cudaGetSymbolAddress((void**)&ahi, g_Ahi);
    cudaGetSymbolAddress((void**)&alo, g_Alo);
    cudaGetSymbolAddress((void**)&bhq, g_BhQ);
    cudaGetSymbolAddress((void**)&bho, g_BhO);

    cudaFuncSetAttribute(gemm_mma,
                         cudaFuncAttributeMaxDynamicSharedMemorySize, GEMM_SMEM);
    cudaFuncSetAttribute(flash_mma,
                         cudaFuncAttributeMaxDynamicSharedMemorySize, FLASH_SMEM);

    /* 1. pack inputs + weights */
    pack_a<<<dim3(KC, MT), 256>>>(hs, ahi, alo);
    pack_bt<<<dim3(NTQ, KC), 256>>>(Wqkv, QKVW, bhq);

    /* 2. QKV projection (+bias) */
    gemm_mma<<<dim3(NTQ, MT), 256, GEMM_SMEM>>>(ahi, alo, bhq, bqkv, qkv, QKVW);

    /* 3. RoPE + fp16 K/V materialization */
    rope3<<<TOK, 128>>>(pos);

    /* 4. causal flash attention -> ctx */
    flash_mma<<<dim3(SSEQ / 128, NHEADS, BB), 256, FLASH_SMEM>>>();

    /* 5. O projection */
    pack_a<<<dim3(KC, MT), 256>>>(ctx, ahi, alo);
    pack_bt<<<dim3(NTO, KC), 256>>>(Wo, HIDDEN, bho);
    gemm_mma<<<dim3(NTO, MT), 256, GEMM_SMEM>>>(ahi, alo, bho, nullptr, out, HIDDEN);
}

// round 15
// speedup vs baseline: 12.0210x; 1.4721x over previous
#include <cuda_runtime.h>
#include <cuda_fp16.h>
#include <math.h>
#include <stdint.h>

#define HIDDEN 4096
#define NHEADS 32
#define HDIM   128
#define BB     2
#define SSEQ   2048
#define TOK    (BB * SSEQ)
#define QKVW   (3 * HIDDEN)

#define MT  (TOK / 128)
#define KC  (HIDDEN / 64)
#define NTQ (QKVW / 128)
#define NTO (HIDDEN / 128)
#define TILE_ELEMS 8192

/* ---------------- device scratch ---------------- */
__device__ float g_qkv[(size_t)TOK * QKVW];
__device__ float g_ctx[(size_t)TOK * HIDDEN];
__device__ __align__(1024) __half g_Ahi[(size_t)MT * KC * TILE_ELEMS];
__device__ __align__(1024) __half g_BhQ[(size_t)NTQ * KC * TILE_ELEMS];
__device__ __align__(1024) __half g_BhO[(size_t)NTO * KC * TILE_ELEMS];
__device__ __align__(256)  __half g_k16[(size_t)BB * NHEADS * SSEQ * HDIM];
__device__ __align__(256)  __half g_v16[(size_t)BB * NHEADS * SSEQ * HDIM];

/* ---------------- helpers ---------------- */
__device__ __forceinline__ uint32_t smem_u32(const void* p) {
    uint32_t a;
    asm("{ .reg .u64 t; cvta.to.shared.u64 t, %1; cvt.u32.u64 %0, t; }"
        : "=r"(a) : "l"(p));
    return a;
}
__device__ __forceinline__ uint32_t sw128(uint32_t b) { return b ^ ((b >> 3) & 0x70); }

__device__ __forceinline__ void cp16(uint32_t d, const void* s) {
    asm volatile("cp.async.cg.shared.global [%0], [%1], 16;" :: "r"(d), "l"(s));
}
#define CP_COMMIT() asm volatile("cp.async.commit_group;" ::: "memory")
template <int N> __device__ __forceinline__ void cp_wait() {
    asm volatile("cp.async.wait_group %0;" :: "n"(N) : "memory");
}

#define LDM4(r, a)                                                            \
    asm volatile("ldmatrix.sync.aligned.m8n8.x4.shared.b16 {%0,%1,%2,%3}, [%4];" \
        : "=r"((r)[0]), "=r"((r)[1]), "=r"((r)[2]), "=r"((r)[3]) : "r"(a))
#define LDM4T(r, a)                                                           \
    asm volatile("ldmatrix.sync.aligned.m8n8.x4.trans.shared.b16 {%0,%1,%2,%3}, [%4];" \
        : "=r"((r)[0]), "=r"((r)[1]), "=r"((r)[2]), "=r"((r)[3]) : "r"(a))

#define MMAH16816(c, a, b0, b1)                                               \
    asm volatile("mma.sync.aligned.m16n8k16.row.col.f32.f16.f16.f32 "         \
        "{%0,%1,%2,%3}, {%4,%5,%6,%7}, {%8,%9}, {%0,%1,%2,%3};"               \
        : "+f"((c)[0]), "+f"((c)[1]), "+f"((c)[2]), "+f"((c)[3])              \
        : "r"((a)[0]), "r"((a)[1]), "r"((a)[2]), "r"((a)[3]), "r"(b0), "r"(b1))

__device__ __forceinline__ uint32_t h2(__half a, __half b) {
    __half2 t; t.x = a; t.y = b;
    return *(uint32_t*)&t;
}

/* ------------------------------------------------------------------ */
/* pack_a: fp32 -> swizzled fp16 tile panel (single term)              */
/* ------------------------------------------------------------------ */
__global__ __launch_bounds__(256) void pack_a(const float* __restrict__ A,
                                              __half* __restrict__ Oh)
{
    const int kc = blockIdx.x, mt = blockIdx.y;
    char* oh = (char*)(Oh + ((size_t)mt * KC + kc) * TILE_ELEMS);
    for (int u = threadIdx.x; u < 1024; u += 256) {
        int r = u >> 3, c8 = (u & 7) * 8;
        const float* src = A + ((size_t)(mt * 128 + r)) * HIDDEN + kc * 64 + c8;
        float4 v0 = *(const float4*)src, v1 = *(const float4*)(src + 4);
        float v[8] = {v0.x, v0.y, v0.z, v0.w, v1.x, v1.y, v1.z, v1.w};
        __align__(16) __half h[8];
#pragma unroll
        for (int j = 0; j < 8; j++) h[j] = __float2half_rn(v[j]);
        uint32_t off = sw128((uint32_t)(r * 128 + c8 * 2));
        *(uint4*)(oh + off) = *(const uint4*)h;
    }
}

/* ------------------------------------------------------------------ */
/* pack_bt: W [K x N] fp32 -> transposed swizzled fp16 panel           */
/* ------------------------------------------------------------------ */
__global__ __launch_bounds__(256) void pack_bt(const float* __restrict__ W, int Ntot,
                                               __half* __restrict__ Oh)
{
    __shared__ float ts[64 * 129];
    const int nt = blockIdx.x, kc = blockIdx.y;
    for (int idx = threadIdx.x; idx < 64 * 128; idx += 256) {
        int k = idx >> 7, n = idx & 127;
        ts[k * 129 + n] = W[(size_t)(kc * 64 + k) * Ntot + nt * 128 + n];
    }
    __syncthreads();
    char* oh = (char*)(Oh + ((size_t)nt * KC + kc) * TILE_ELEMS);
    for (int u = threadIdx.x; u < 1024; u += 256) {
        int n = u >> 3, k8 = (u & 7) * 8;
        __align__(16) __half h[8];
#pragma unroll
        for (int j = 0; j < 8; j++)
            h[j] = __float2half_rn(ts[(k8 + j) * 129 + n]);
        uint32_t off = sw128((uint32_t)(n * 128 + k8 * 2));
        *(uint4*)(oh + off) = *(const uint4*)h;
    }
}

/* ------------------------------------------------------------------ */
/* fp16 single-term mma GEMM: C = Ah @ Bh^T.                           */
/* 256 threads = 8 warps (2m x 4n); warp tile 64x32.                   */
/* 3-stage cp.async pipeline, 32KB/stage (Ah | Bh).                    */
/* ------------------------------------------------------------------ */
#define NSTG 3
#define STAGE_BYTES 32768
#define GEMM_SMEM (NSTG * STAGE_BYTES)

__global__ __launch_bounds__(256) void gemm_mma(
    const __half* __restrict__ Ah, const __half* __restrict__ Bh,
    const float* __restrict__ bias, float* __restrict__ C, int Ntot)
{
    extern __shared__ char smem[];
    const uint32_t sb = smem_u32(smem);
    const int tid = threadIdx.x, wid = tid >> 5, lane = tid & 31;
    const int wm = wid & 1, wn = wid >> 1;
    const int nt = blockIdx.x, mt = blockIdx.y;

    const char* srcA = (const char*)(Ah + (size_t)mt * KC * TILE_ELEMS);
    const char* srcB = (const char*)(Bh + (size_t)nt * KC * TILE_ELEMS);

    float acc[4][4][4];
#pragma unroll
    for (int i = 0; i < 4; i++)
#pragma unroll
        for (int j = 0; j < 4; j++)
#pragma unroll
            for (int q = 0; q < 4; q++) acc[i][j][q] = 0.f;

    int rowA[4]; uint32_t offA[4];
#pragma unroll
    for (int mt2 = 0; mt2 < 4; mt2++) {
        rowA[mt2] = wm * 64 + mt2 * 16 + (lane & 15);
        offA[mt2] = (uint32_t)rowA[mt2] * 128;
    }
    const uint32_t cbA_base = (uint32_t)((lane >> 4) << 4);
    int rowB[2]; uint32_t offB[2];
#pragma unroll
    for (int np = 0; np < 2; np++) {
        rowB[np] = wn * 32 + np * 16 + ((lane & 7) | ((lane >> 4) << 3));
        offB[np] = (uint32_t)rowB[np] * 128;
    }
    const uint32_t cbB_base = (uint32_t)(((lane >> 3) & 1) << 4);

    auto copy_stage = [&](int j, int s) {
        size_t o = (size_t)j * 16384;
        uint32_t dst = sb + s * STAGE_BYTES + tid * 16;
#pragma unroll
        for (int it = 0; it < 4; it++)
            cp16(dst + it * 4096, srcA + o + tid * 16 + (size_t)it * 4096);
#pragma unroll
        for (int it = 0; it < 4; it++)
            cp16(dst + 16384 + it * 4096, srcB + o + tid * 16 + (size_t)it * 4096);
    };

    copy_stage(0, 0); CP_COMMIT();
    copy_stage(1, 1); CP_COMMIT();

    for (int i = 0; i < KC; i++) {
        int s = i % NSTG;
        if (i + 2 < KC) { copy_stage(i + 2, (i + 2) % NSTG); CP_COMMIT(); cp_wait<2>(); }
        else if (i + 1 < KC) { cp_wait<1>(); }
        else { cp_wait<0>(); }
        __syncthreads();

        const uint32_t aHi = sb + s * STAGE_BYTES;
        const uint32_t bHi = aHi + 16384;

#pragma unroll
        for (int ks = 0; ks < 4; ks++) {
            uint32_t ah[4][4];
#pragma unroll
            for (int mt2 = 0; mt2 < 4; mt2++) {
                uint32_t cb = (uint32_t)(ks * 32) + cbA_base;
                uint32_t off = offA[mt2] + (cb ^ (((uint32_t)rowA[mt2] & 7) << 4));
                LDM4(ah[mt2], aHi + off);
            }
            uint32_t bh[4][2];
#pragma unroll
            for (int np = 0; np < 2; np++) {
                uint32_t cb = (uint32_t)(ks * 32) + cbB_base;
                uint32_t off = offB[np] + (cb ^ (((uint32_t)rowB[np] & 7) << 4));
                uint32_t t[4];
                LDM4(t, bHi + off);
                bh[np * 2][0] = t[0]; bh[np * 2][1] = t[1];
                bh[np * 2 + 1][0] = t[2]; bh[np * 2 + 1][1] = t[3];
            }
#pragma unroll
            for (int mt2 = 0; mt2 < 4; mt2++)
#pragma unroll
                for (int nt2 = 0; nt2 < 4; nt2++)
                    MMAH16816(acc[mt2][nt2], ah[mt2], bh[nt2][0], bh[nt2][1]);
        }
        __syncthreads();
    }

    const int r0 = mt * 128 + wm * 64 + (lane >> 2);
    const int c0 = nt * 128 + wn * 32 + (lane & 3) * 2;
#pragma unroll
    for (int mt2 = 0; mt2 < 4; mt2++) {
#pragma unroll
        for (int nt2 = 0; nt2 < 4; nt2++) {
            int row = r0 + mt2 * 16;
            int col = c0 + nt2 * 8;
            float b0 = 0.f, b1 = 0.f;
            if (bias) { b0 = bias[col]; b1 = bias[col + 1]; }
            float2* p0 = (float2*)&C[(size_t)row * Ntot + col];
            *p0 = make_float2(acc[mt2][nt2][0] + b0, acc[mt2][nt2][1] + b1);
            float2* p1 = (float2*)&C[(size_t)(row + 8) * Ntot + col];
            *p1 = make_float2(acc[mt2][nt2][2] + b0, acc[mt2][nt2][3] + b1);
        }
    }
}

/* ------------------------------------------------------------------ */
/* rope3: rope q in place (fp32); rope k -> g_k16 fp16 [b][h][s][d];   */
/* copy v -> g_v16 fp16.                                               */
/* ------------------------------------------------------------------ */
__global__ __launch_bounds__(128) void rope3(const int* __restrict__ positions)
{
    __shared__ float cs[64], sn[64];
    const int tok = blockIdx.x;
    const int b = tok >> 11, s = tok & (SSEQ - 1);
    if (threadIdx.x < 64) {
        int p = positions[tok];
        double inv = exp(-(double)threadIdx.x * (9.210340371976184 / 64.0));
        double a = (double)p * inv;
        cs[threadIdx.x] = (float)cos(a);
        sn[threadIdx.x] = (float)sin(a);
    }
    __syncthreads();
    const size_t base = (size_t)tok * QKVW;
    for (int i = threadIdx.x; i < NHEADS * 64; i += 128) {
        int h = i >> 6, d = i & 63;
        float c = cs[d], sv = sn[d];
        size_t o = base + (size_t)h * HDIM + d;
        float x1 = g_qkv[o], x2 = g_qkv[o + 64];
        g_qkv[o]      = x1 * c - x2 * sv;
        g_qkv[o + 64] = x2 * c + x1 * sv;
        size_t ko = o + HIDDEN;
        x1 = g_qkv[ko]; x2 = g_qkv[ko + 64];
        size_t kb = ((size_t)(b * NHEADS + h) * SSEQ + s) * HDIM;
        g_k16[kb + d]      = __float2half_rn(x1 * c - x2 * sv);
        g_k16[kb + d + 64] = __float2half_rn(x2 * c + x1 * sv);
    }
    for (int i = threadIdx.x; i < HIDDEN / 4; i += 128) {
        float4 v = *(const float4*)&g_qkv[base + 2 * HIDDEN + (size_t)i * 4];
        int h = (i * 4) >> 7, d = (i * 4) & 127;
        size_t vb = ((size_t)(b * NHEADS + h) * SSEQ + s) * HDIM + d;
        *(uint2*)&g_v16[vb] = make_uint2(
            h2(__float2half_rn(v.x), __float2half_rn(v.y)),
            h2(__float2half_rn(v.z), __float2half_rn(v.w)));
    }
}

/* ------------------------------------------------------------------ */
/* Flash v2 (unchanged from round 13): BQ=128, 256 threads.            */
/* Q = Qh+Ql fp16 (regs); K,V fp16 via double-buffered cp.async.       */
/* ------------------------------------------------------------------ */
#define PITB   272
#define KVHALF 17408
#define KVSTG  (2 * KVHALF)
#define FLASH_SMEM (2 * KVSTG)

__global__ __launch_bounds__(256) void flash_mma()
{
    extern __shared__ char sm[];
    const uint32_t sb = smem_u32(sm);
    const uint32_t QhS = sb;

    const int tid = threadIdx.x, w = tid >> 5, lane = tid & 31;
    const int qt = blockIdx.x, h = blockIdx.y, b = blockIdx.z;
    const size_t tokbase = (size_t)b * SSEQ;
    const size_t kvhead = (size_t)(b * NHEADS + h) * SSEQ;
    const float scale = 0.08838834764831845f;

    for (int i = tid; i < 128 * 32; i += 256) {
        int r = i >> 5, c4 = i & 31;
        float4 v = *(const float4*)&g_qkv[(tokbase + qt * 128 + r) * QKVW +
                                          (size_t)h * HDIM + c4 * 4];
        __half hx = __float2half_rn(v.x), hy = __float2half_rn(v.y);
        __half hz = __float2half_rn(v.z), hw = __float2half_rn(v.w);
        *(uint2*)(sm + r * PITB + c4 * 8) = make_uint2(h2(hx, hy), h2(hz, hw));
        *(uint2*)(sm + 34816 + r * PITB + c4 * 8) = make_uint2(
            h2(__float2half_rn(v.x - __half2float(hx)),
               __float2half_rn(v.y - __half2float(hy))),
            h2(__float2half_rn(v.z - __half2float(hz)),
               __float2half_rn(v.w - __half2float(hw))));
    }
    __syncthreads();

    uint32_t qh[8][4], ql[8][4];
#pragma unroll
    for (int kc = 0; kc < 8; kc++) {
        uint32_t addr = QhS + (uint32_t)(w * 16 + (lane & 15)) * PITB +
                        (uint32_t)((kc * 2 + (lane >> 4)) * 16);
        LDM4(qh[kc], addr);
        LDM4(ql[kc], addr + 34816);
    }
    __syncthreads();

    float O[16][4];
#pragma unroll
    for (int i = 0; i < 16; i++)
#pragma unroll
        for (int c = 0; c < 4; c++) O[i][c] = 0.f;
    float mrow0 = -INFINITY, mrow1 = -INFINITY, lrow0 = 0.f, lrow1 = 0.f;

    const int r0 = lane >> 2;
    const int ncol = (lane & 3) * 2;
    const int mg0 = qt * 128 + w * 16 + r0, mg1 = mg0 + 8;

    auto load_kv = [&](int kt, int stg) {
        const char* kb = (const char*)(g_k16 + (kvhead + kt * 64) * HDIM);
        const char* vb = (const char*)(g_v16 + (kvhead + kt * 64) * HDIM);
        uint32_t ks = sb + stg * KVSTG, vs = ks + KVHALF;
        for (int i = tid; i < 1024; i += 256) {
            int r = i >> 4, c = i & 15;
            cp16(ks + r * PITB + c * 16, kb + r * 256 + c * 16);
            cp16(vs + r * PITB + c * 16, vb + r * 256 + c * 16);
        }
    };

    const int ktmax = 2 * qt + 1;
    load_kv(0, 0); CP_COMMIT();

    for (int kt = 0; kt <= ktmax; kt++) {
        int stg = kt & 1;
        if (kt < ktmax) { load_kv(kt + 1, stg ^ 1); CP_COMMIT(); cp_wait<1>(); }
        else            { cp_wait<0>(); }
        __syncthreads();

        if (kt * 64 <= qt * 128 + w * 16 + 15) {
            const uint32_t KS = sb + stg * KVSTG, VS = KS + KVHALF;

            float s[8][4];
#pragma unroll
            for (int i = 0; i < 8; i++)
#pragma unroll
                for (int c = 0; c < 4; c++) s[i][c] = 0.f;

#pragma unroll
            for (int kc = 0; kc < 8; kc++) {
#pragma unroll
                for (int nc2 = 0; nc2 < 4; nc2++) {
                    int nrow = nc2 * 16 + ((lane >> 4) << 3) + (lane & 7);
                    int col16 = kc * 2 + ((lane >> 3) & 1);
                    uint32_t addr = KS + (uint32_t)nrow * PITB + (uint32_t)col16 * 16;
                    uint32_t k4[4];
                    LDM4(k4, addr);
                    MMAH16816(s[nc2 * 2],     qh[kc], k4[0], k4[1]);
                    MMAH16816(s[nc2 * 2],     ql[kc], k4[0], k4[1]);
                    MMAH16816(s[nc2 * 2 + 1], qh[kc], k4[2], k4[3]);
                    MMAH16816(s[nc2 * 2 + 1], ql[kc], k4[2], k4[3]);
                }
            }

            const bool crossing = (kt >= 2 * qt);
#pragma unroll
            for (int nt = 0; nt < 8; nt++) {
#pragma unroll
                for (int c = 0; c < 4; c++) s[nt][c] *= scale;
                if (crossing) {
                    int n0 = kt * 64 + nt * 8 + ncol;
                    if (n0     > mg0) s[nt][0] = -1e30f;
                    if (n0 + 1 > mg0) s[nt][1] = -1e30f;
                    if (n0     > mg1) s[nt][2] = -1e30f;
                    if (n0 + 1 > mg1) s[nt][3] = -1e30f;
                }
            }

            float mx0 = mrow0, mx1 = mrow1;
#pragma unroll
            for (int nt = 0; nt < 8; nt++) {
                mx0 = fmaxf(mx0, fmaxf(s[nt][0], s[nt][1]));
                mx1 = fmaxf(mx1, fmaxf(s[nt][2], s[nt][3]));
            }
            mx0 = fmaxf(mx0, __shfl_xor_sync(0xffffffffu, mx0, 1));
            mx0 = fmaxf(mx0, __shfl_xor_sync(0xffffffffu, mx0, 2));
            mx1 = fmaxf(mx1, __shfl_xor_sync(0xffffffffu, mx1, 1));
            mx1 = fmaxf(mx1, __shfl_xor_sync(0xffffffffu, mx1, 2));
            float a0 = __expf(mrow0 - mx0), a1 = __expf(mrow1 - mx1);
            mrow0 = mx0; mrow1 = mx1;
            float ps0 = 0.f, ps1 = 0.f;
#pragma unroll
            for (int nt = 0; nt < 8; nt++) {
                s[nt][0] = __expf(s[nt][0] - mx0);
                s[nt][1] = __expf(s[nt][1] - mx0);
                s[nt][2] = __expf(s[nt][2] - mx1);
                s[nt][3] = __expf(s[nt][3] - mx1);
                ps0 += s[nt][0] + s[nt][1];
                ps1 += s[nt][2] + s[nt][3];
            }
            ps0 += __shfl_xor_sync(0xffffffffu, ps0, 1);
            ps0 += __shfl_xor_sync(0xffffffffu, ps0, 2);
            ps1 += __shfl_xor_sync(0xffffffffu, ps1, 1);
            ps1 += __shfl_xor_sync(0xffffffffu, ps1, 2);
            lrow0 = lrow0 * a0 + ps0;
            lrow1 = lrow1 * a1 + ps1;
#pragma unroll
            for (int dn = 0; dn < 16; dn++) {
                O[dn][0] *= a0; O[dn][1] *= a0;
                O[dn][2] *= a1; O[dn][3] *= a1;
            }

#pragma unroll
            for (int pk = 0; pk < 4; pk++) {
                uint32_t pa_h[4], pa_l[4];
#pragma unroll
                for (int half = 0; half < 2; half++) {
                    int nt = pk * 2 + half;
                    __half h0 = __float2half_rn(s[nt][0]);
                    __half h1 = __float2half_rn(s[nt][1]);
                    __half h2_ = __float2half_rn(s[nt][2]);
                    __half h3 = __float2half_rn(s[nt][3]);
                    pa_h[half * 2]     = h2(h0, h1);
                    pa_h[half * 2 + 1] = h2(h2_, h3);
                    pa_l[half * 2]     = h2(__float2half_rn(s[nt][0] - __half2float(h0)),
                                            __float2half_rn(s[nt][1] - __half2float(h1)));
                    pa_l[half * 2 + 1] = h2(__float2half_rn(s[nt][2] - __half2float(h2_)),
                                            __float2half_rn(s[nt][3] - __half2float(h3)));
                }
#pragma unroll
                for (int dn2 = 0; dn2 < 8; dn2++) {
                    uint32_t addr = VS + (uint32_t)(pk * 16 + (lane & 15)) * PITB +
                                    (uint32_t)((dn2 * 2 + (lane >> 4)) * 16);
                    uint32_t v4[4];
                    LDM4T(v4, addr);
                    MMAH16816(O[dn2 * 2],     pa_h, v4[0], v4[1]);
                    MMAH16816(O[dn2 * 2],     pa_l, v4[0], v4[1]);
                    MMAH16816(O[dn2 * 2 + 1], pa_h, v4[2], v4[3]);
                    MMAH16816(O[dn2 * 2 + 1], pa_l, v4[2], v4[3]);
                }
            }
        }
        __syncthreads();
    }

    float il0 = 1.f / lrow0, il1 = 1.f / lrow1;
    const int m_glob0 = qt * 128 + w * 16 + r0;
    const int m_glob1 = m_glob0 + 8;
#pragma unroll
    for (int dn = 0; dn < 16; dn++) {
        int d = dn * 8 + ncol;
        *(float2*)&g_ctx[(tokbase + m_glob0) * HIDDEN + (size_t)h * HDIM + d] =
            make_float2(O[dn][0] * il0, O[dn][1] * il0);
        *(float2*)&g_ctx[(tokbase + m_glob1) * HIDDEN + (size_t)h * HDIM + d] =
            make_float2(O[dn][2] * il1, O[dn][3] * il1);
    }
}

/* ------------------------------------------------------------------ */
extern "C" void kernel_launch(void* const* d_in, const int* in_sizes, int n_in,
                              void* d_out, int out_size)
{
    (void)in_sizes; (void)n_in; (void)out_size;
    const float* hs   = (const float*)d_in[0];
    const int*   pos  = (const int*)  d_in[1];
    const float* Wqkv = (const float*)d_in[2];
    const float* bqkv = (const float*)d_in[3];
    const float* Wo   = (const float*)d_in[4];
    float* out = (float*)d_out;

    float *qkv, *ctx;
    __half *ahi, *bhq, *bho;
    cudaGetSymbolAddress((void**)&qkv, g_qkv);
    cudaGetSymbolAddress((void**)&ctx, g_ctx);
    cudaGetSymbolAddress((void**)&ahi, g_Ahi);
    cudaGetSymbolAddress((void**)&bhq, g_BhQ);
    cudaGetSymbolAddress((void**)&bho, g_BhO);

    cudaFuncSetAttribute(gemm_mma,
                         cudaFuncAttributeMaxDynamicSharedMemorySize, GEMM_SMEM);
    cudaFuncSetAttribute(flash_mma,
                         cudaFuncAttributeMaxDynamicSharedMemorySize, FLASH_SMEM);

    /* 1. pack inputs + weights */
    pack_a<<<dim3(KC, MT), 256>>>(hs, ahi);
    pack_bt<<<dim3(NTQ, KC), 256>>>(Wqkv, QKVW, bhq);

    /* 2. QKV projection (+bias) */
    gemm_mma<<<dim3(NTQ, MT), 256, GEMM_SMEM>>>(ahi, bhq, bqkv, qkv, QKVW);

    /* 3. RoPE + fp16 K/V materialization */
    rope3<<<TOK, 128>>>(pos);

    /* 4. causal flash attention -> ctx */
    flash_mma<<<dim3(SSEQ / 128, NHEADS, BB), 256, FLASH_SMEM>>>();

    /* 5. O projection */
    pack_a<<<dim3(KC, MT), 256>>>(ctx, ahi);
    pack_bt<<<dim3(NTO, KC), 256>>>(Wo, HIDDEN, bho);
    gemm_mma<<<dim3(NTO, MT), 256, GEMM_SMEM>>>(ahi, bho, nullptr, out, HIDDEN);
}

// round 16
// speedup vs baseline: 12.5256x; 1.0420x over previous
#include <cuda_runtime.h>
#include <cuda_fp16.h>
#include <math.h>
#include <stdint.h>

#define HIDDEN 4096
#define NHEADS 32
#define HDIM   128
#define BB     2
#define SSEQ   2048
#define TOK    (BB * SSEQ)
#define QKVW   (3 * HIDDEN)

#define MT  (TOK / 128)
#define KC  (HIDDEN / 64)
#define NTQ (QKVW / 128)
#define NTO (HIDDEN / 128)
#define TILE_ELEMS 8192

/* ---------------- device scratch ---------------- */
__device__ float2 g_rope[(size_t)TOK * 64];                       /* cos,sin */
__device__ __align__(1024) __half g_Ahid[(size_t)MT * KC * TILE_ELEMS];
__device__ __align__(1024) __half g_Actx[(size_t)MT * KC * TILE_ELEMS];
__device__ __align__(1024) __half g_BhQ[(size_t)NTQ * KC * TILE_ELEMS];
__device__ __align__(1024) __half g_BhO[(size_t)NTO * KC * TILE_ELEMS];
__device__ __align__(256)  __half g_q16h[(size_t)BB * NHEADS * SSEQ * HDIM];
__device__ __align__(256)  __half g_q16l[(size_t)BB * NHEADS * SSEQ * HDIM];
__device__ __align__(256)  __half g_k16[(size_t)BB * NHEADS * SSEQ * HDIM];
__device__ __align__(256)  __half g_v16[(size_t)BB * NHEADS * SSEQ * HDIM];

/* ---------------- helpers ---------------- */
__device__ __forceinline__ uint32_t smem_u32(const void* p) {
    uint32_t a;
    asm("{ .reg .u64 t; cvta.to.shared.u64 t, %1; cvt.u32.u64 %0, t; }"
        : "=r"(a) : "l"(p));
    return a;
}
__device__ __forceinline__ uint32_t sw128(uint32_t b) { return b ^ ((b >> 3) & 0x70); }

__device__ __forceinline__ void cp16(uint32_t d, const void* s) {
    asm volatile("cp.async.cg.shared.global [%0], [%1], 16;" :: "r"(d), "l"(s));
}
#define CP_COMMIT() asm volatile("cp.async.commit_group;" ::: "memory")
template <int N> __device__ __forceinline__ void cp_wait() {
    asm volatile("cp.async.wait_group %0;" :: "n"(N) : "memory");
}

#define LDM4(r, a)                                                            \
    asm volatile("ldmatrix.sync.aligned.m8n8.x4.shared.b16 {%0,%1,%2,%3}, [%4];" \
        : "=r"((r)[0]), "=r"((r)[1]), "=r"((r)[2]), "=r"((r)[3]) : "r"(a))
#define LDM4T(r, a)                                                           \
    asm volatile("ldmatrix.sync.aligned.m8n8.x4.trans.shared.b16 {%0,%1,%2,%3}, [%4];" \
        : "=r"((r)[0]), "=r"((r)[1]), "=r"((r)[2]), "=r"((r)[3]) : "r"(a))

#define MMAH16816(c, a, b0, b1)                                               \
    asm volatile("mma.sync.aligned.m16n8k16.row.col.f32.f16.f16.f32 "         \
        "{%0,%1,%2,%3}, {%4,%5,%6,%7}, {%8,%9}, {%0,%1,%2,%3};"               \
        : "+f"((c)[0]), "+f"((c)[1]), "+f"((c)[2]), "+f"((c)[3])              \
        : "r"((a)[0]), "r"((a)[1]), "r"((a)[2]), "r"((a)[3]), "r"(b0), "r"(b1))

__device__ __forceinline__ uint32_t h2(__half a, __half b) {
    __half2 t; t.x = a; t.y = b;
    return *(uint32_t*)&t;
}
__device__ __forceinline__ __half2 mk2(float a, float b) {
    __half2 t; t.x = __float2half_rn(a); t.y = __float2half_rn(b);
    return t;
}

/* ------------------------------------------------------------------ */
/* rope_table: cos/sin per (token, freq) once.                         */
/* ------------------------------------------------------------------ */
__global__ __launch_bounds__(64) void rope_table(const int* __restrict__ positions)
{
    const int tok = blockIdx.x, t = threadIdx.x;
    int p = positions[tok];
    double inv = exp(-(double)t * (9.210340371976184 / 64.0));
    double a = (double)p * inv;
    g_rope[(size_t)tok * 64 + t] = make_float2((float)cos(a), (float)sin(a));
}

/* ------------------------------------------------------------------ */
/* pack_a: fp32 -> swizzled fp16 tile panel                            */
/* ------------------------------------------------------------------ */
__global__ __launch_bounds__(256) void pack_a(const float* __restrict__ A,
                                              __half* __restrict__ Oh)
{
    const int kc = blockIdx.x, mt = blockIdx.y;
    char* oh = (char*)(Oh + ((size_t)mt * KC + kc) * TILE_ELEMS);
    for (int u = threadIdx.x; u < 1024; u += 256) {
        int r = u >> 3, c8 = (u & 7) * 8;
        const float* src = A + ((size_t)(mt * 128 + r)) * HIDDEN + kc * 64 + c8;
        float4 v0 = *(const float4*)src, v1 = *(const float4*)(src + 4);
        float v[8] = {v0.x, v0.y, v0.z, v0.w, v1.x, v1.y, v1.z, v1.w};
        __align__(16) __half h[8];
#pragma unroll
        for (int j = 0; j < 8; j++) h[j] = __float2half_rn(v[j]);
        uint32_t off = sw128((uint32_t)(r * 128 + c8 * 2));
        *(uint4*)(oh + off) = *(const uint4*)h;
    }
}

/* ------------------------------------------------------------------ */
/* pack_bt: W [K x N] fp32 -> transposed swizzled fp16 panel           */
/* ------------------------------------------------------------------ */
__global__ __launch_bounds__(256) void pack_bt(const float* __restrict__ W, int Ntot,
                                               __half* __restrict__ Oh)
{
    __shared__ float ts[64 * 129];
    const int nt = blockIdx.x, kc = blockIdx.y;
    for (int idx = threadIdx.x; idx < 64 * 128; idx += 256) {
        int k = idx >> 7, n = idx & 127;
        ts[k * 129 + n] = W[(size_t)(kc * 64 + k) * Ntot + nt * 128 + n];
    }
    __syncthreads();
    char* oh = (char*)(Oh + ((size_t)nt * KC + kc) * TILE_ELEMS);
    for (int u = threadIdx.x; u < 1024; u += 256) {
        int n = u >> 3, k8 = (u & 7) * 8;
        __align__(16) __half h[8];
#pragma unroll
        for (int j = 0; j < 8; j++)
            h[j] = __float2half_rn(ts[(k8 + j) * 129 + n]);
        uint32_t off = sw128((uint32_t)(n * 128 + k8 * 2));
        *(uint4*)(oh + off) = *(const uint4*)h;
    }
}

/* ------------------------------------------------------------------ */
/* GEMM mainloop shared bits                                           */
/* ------------------------------------------------------------------ */
#define NSTG 3
#define STAGE_BYTES 32768
#define GEMM_SMEM (NSTG * STAGE_BYTES)
#define SP 130   /* fp32 smem pitch for fused epilogue */

#define GEMM_MAINLOOP(ACC)                                                     \
    int rowA[4]; uint32_t offA[4];                                             \
    _Pragma("unroll")                                                          \
    for (int mt2 = 0; mt2 < 4; mt2++) {                                        \
        rowA[mt2] = wm * 64 + mt2 * 16 + (lane & 15);                          \
        offA[mt2] = (uint32_t)rowA[mt2] * 128;                                 \
    }                                                                          \
    const uint32_t cbA_base = (uint32_t)((lane >> 4) << 4);                    \
    int rowB[2]; uint32_t offB[2];                                             \
    _Pragma("unroll")                                                          \
    for (int np = 0; np < 2; np++) {                                           \
        rowB[np] = wn * 32 + np * 16 + ((lane & 7) | ((lane >> 4) << 3));      \
        offB[np] = (uint32_t)rowB[np] * 128;                                   \
    }                                                                          \
    const uint32_t cbB_base = (uint32_t)(((lane >> 3) & 1) << 4);              \
    auto copy_stage = [&](int j, int s) {                                      \
        size_t o = (size_t)j * 16384;                                          \
        uint32_t dst = sb + s * STAGE_BYTES + tid * 16;                        \
        _Pragma("unroll")                                                      \
        for (int it = 0; it < 4; it++)                                         \
            cp16(dst + it * 4096, srcA + o + tid * 16 + (size_t)it * 4096);    \
        _Pragma("unroll")                                                      \
        for (int it = 0; it < 4; it++)                                         \
            cp16(dst + 16384 + it * 4096, srcB + o + tid * 16 + (size_t)it * 4096); \
    };                                                                         \
    copy_stage(0, 0); CP_COMMIT();                                             \
    copy_stage(1, 1); CP_COMMIT();                                             \
    for (int i = 0; i < KC; i++) {                                             \
        int s = i % NSTG;                                                      \
        if (i + 2 < KC) { copy_stage(i + 2, (i + 2) % NSTG); CP_COMMIT(); cp_wait<2>(); } \
        else if (i + 1 < KC) { cp_wait<1>(); }                                 \
        else { cp_wait<0>(); }                                                 \
        __syncthreads();                                                       \
        const uint32_t aHi = sb + s * STAGE_BYTES;                             \
        const uint32_t bHi = aHi + 16384;                                      \
        _Pragma("unroll")                                                      \
        for (int ks = 0; ks < 4; ks++) {                                       \
            uint32_t ah[4][4];                                                 \
            _Pragma("unroll")                                                  \
            for (int mt2 = 0; mt2 < 4; mt2++) {                                \
                uint32_t cb = (uint32_t)(ks * 32) + cbA_base;                  \
                uint32_t off = offA[mt2] + (cb ^ (((uint32_t)rowA[mt2] & 7) << 4)); \
                LDM4(ah[mt2], aHi + off);                                      \
            }                                                                  \
            uint32_t bh[4][2];                                                 \
            _Pragma("unroll")                                                  \
            for (int np = 0; np < 2; np++) {                                   \
                uint32_t cb = (uint32_t)(ks * 32) + cbB_base;                  \
                uint32_t off = offB[np] + (cb ^ (((uint32_t)rowB[np] & 7) << 4)); \
                uint32_t t[4];                                                 \
                LDM4(t, bHi + off);                                            \
                bh[np * 2][0] = t[0]; bh[np * 2][1] = t[1];                    \
                bh[np * 2 + 1][0] = t[2]; bh[np * 2 + 1][1] = t[3];            \
            }                                                                  \
            _Pragma("unroll")                                                  \
            for (int mt2 = 0; mt2 < 4; mt2++)                                  \
                _Pragma("unroll")                                              \
                for (int nt2 = 0; nt2 < 4; nt2++)                              \
                    MMAH16816(ACC[mt2][nt2], ah[mt2], bh[nt2][0], bh[nt2][1]); \
        }                                                                      \
        __syncthreads();                                                       \
    }

/* ------------------------------------------------------------------ */
/* gemm_mma: generic epilogue (O projection -> fp32 C)                 */
/* ------------------------------------------------------------------ */
__global__ __launch_bounds__(256) void gemm_mma(
    const __half* __restrict__ Ah, const __half* __restrict__ Bh,
    float* __restrict__ C, int Ntot)
{
    extern __shared__ char smem[];
    const uint32_t sb = smem_u32(smem);
    const int tid = threadIdx.x, wid = tid >> 5, lane = tid & 31;
    const int wm = wid & 1, wn = wid >> 1;
    const int nt = blockIdx.x, mt = blockIdx.y;
    const char* srcA = (const char*)(Ah + (size_t)mt * KC * TILE_ELEMS);
    const char* srcB = (const char*)(Bh + (size_t)nt * KC * TILE_ELEMS);

    float acc[4][4][4];
#pragma unroll
    for (int i = 0; i < 4; i++)
#pragma unroll
        for (int j = 0; j < 4; j++)
#pragma unroll
            for (int q = 0; q < 4; q++) acc[i][j][q] = 0.f;

    GEMM_MAINLOOP(acc)

    const int r0 = mt * 128 + wm * 64 + (lane >> 2);
    const int c0 = nt * 128 + wn * 32 + (lane & 3) * 2;
#pragma unroll
    for (int mt2 = 0; mt2 < 4; mt2++) {
#pragma unroll
        for (int nt2 = 0; nt2 < 4; nt2++) {
            int row = r0 + mt2 * 16;
            int col = c0 + nt2 * 8;
            *(float2*)&C[(size_t)row * Ntot + col] =
                make_float2(acc[mt2][nt2][0], acc[mt2][nt2][1]);
            *(float2*)&C[(size_t)(row + 8) * Ntot + col] =
                make_float2(acc[mt2][nt2][2], acc[mt2][nt2][3]);
        }
    }
}

/* ------------------------------------------------------------------ */
/* gemm_qkv: fused epilogue. nt<32: q (+bias, rope, fp16 hi/lo);       */
/* nt in [32,64): k (+bias, rope, fp16); nt>=64: v (+bias, fp16).      */
/* ------------------------------------------------------------------ */
__global__ __launch_bounds__(256) void gemm_qkv(
    const __half* __restrict__ Ah, const __half* __restrict__ Bh,
    const float* __restrict__ bias)
{
    extern __shared__ char smem[];
    const uint32_t sb = smem_u32(smem);
    const int tid = threadIdx.x, wid = tid >> 5, lane = tid & 31;
    const int wm = wid & 1, wn = wid >> 1;
    const int nt = blockIdx.x, mt = blockIdx.y;
    const char* srcA = (const char*)(Ah + (size_t)mt * KC * TILE_ELEMS);
    const char* srcB = (const char*)(Bh + (size_t)nt * KC * TILE_ELEMS);

    float acc[4][4][4];
#pragma unroll
    for (int i = 0; i < 4; i++)
#pragma unroll
        for (int j = 0; j < 4; j++)
#pragma unroll
            for (int q = 0; q < 4; q++) acc[i][j][q] = 0.f;

    GEMM_MAINLOOP(acc)

    /* bias */
    const int c0l = wn * 32 + (lane & 3) * 2;   /* local col in 128-tile */
#pragma unroll
    for (int nt2 = 0; nt2 < 4; nt2++) {
        float b0 = bias[nt * 128 + c0l + nt2 * 8];
        float b1 = bias[nt * 128 + c0l + nt2 * 8 + 1];
#pragma unroll
        for (int mt2 = 0; mt2 < 4; mt2++) {
            acc[mt2][nt2][0] += b0; acc[mt2][nt2][1] += b1;
            acc[mt2][nt2][2] += b0; acc[mt2][nt2][3] += b1;
        }
    }

    const int r0l = wm * 64 + (lane >> 2);      /* local row in 128-tile */

    if (nt >= 64) {
        /* ---- v: direct fp16 store, no rope ---- */
        const int h = nt - 64;
#pragma unroll
        for (int mt2 = 0; mt2 < 4; mt2++) {
#pragma unroll
            for (int nt2 = 0; nt2 < 4; nt2++) {
                int d = c0l + nt2 * 8;
#pragma unroll
                for (int hf = 0; hf < 2; hf++) {
                    int tok = mt * 128 + r0l + mt2 * 16 + hf * 8;
                    int b = tok >> 11, s = tok & (SSEQ - 1);
                    size_t base = ((size_t)(b * NHEADS + h) * SSEQ + s) * HDIM + d;
                    *(__half2*)&g_v16[base] =
                        mk2(acc[mt2][nt2][hf * 2], acc[mt2][nt2][hf * 2 + 1]);
                }
            }
        }
        return;
    }

    /* ---- q/k: stage tile in smem, rope, fp16 store ---- */
    float* tf = (float*)smem;
#pragma unroll
    for (int mt2 = 0; mt2 < 4; mt2++) {
#pragma unroll
        for (int nt2 = 0; nt2 < 4; nt2++) {
            int c = c0l + nt2 * 8;
            *(float2*)&tf[(r0l + mt2 * 16) * SP + c] =
                make_float2(acc[mt2][nt2][0], acc[mt2][nt2][1]);
            *(float2*)&tf[(r0l + mt2 * 16 + 8) * SP + c] =
                make_float2(acc[mt2][nt2][2], acc[mt2][nt2][3]);
        }
    }
    __syncthreads();

    const bool is_q = (nt < 32);
    const int h = is_q ? nt : nt - 32;
    for (int idx = tid; idx < 128 * 32; idx += 256) {
        int r = idx >> 5, dp = (idx & 31) * 2;
        int tok = mt * 128 + r;
        int b = tok >> 11, s = tok & (SSEQ - 1);
        float x1a = tf[r * SP + dp],      x1b = tf[r * SP + dp + 1];
        float x2a = tf[r * SP + dp + 64], x2b = tf[r * SP + dp + 65];
        float2 t0 = g_rope[(size_t)tok * 64 + dp];
        float2 t1 = g_rope[(size_t)tok * 64 + dp + 1];
        float y1a = x1a * t0.x - x2a * t0.y;
        float y2a = x2a * t0.x + x1a * t0.y;
        float y1b = x1b * t1.x - x2b * t1.y;
        float y2b = x2b * t1.x + x1b * t1.y;
        size_t base = ((size_t)(b * NHEADS + h) * SSEQ + s) * HDIM;
        if (is_q) {
            __half ha = __float2half_rn(y1a), hb = __float2half_rn(y1b);
            __half ga = __float2half_rn(y2a), gb = __float2half_rn(y2b);
            *(uint32_t*)&g_q16h[base + dp]      = h2(ha, hb);
            *(uint32_t*)&g_q16h[base + dp + 64] = h2(ga, gb);
            *(uint32_t*)&g_q16l[base + dp] =
                h2(__float2half_rn(y1a - __half2float(ha)),
                   __float2half_rn(y1b - __half2float(hb)));
            *(uint32_t*)&g_q16l[base + dp + 64] =
                h2(__float2half_rn(y2a - __half2float(ga)),
                   __float2half_rn(y2b - __half2float(gb)));
        } else {
            *(__half2*)&g_k16[base + dp]      = mk2(y1a, y1b);
            *(__half2*)&g_k16[base + dp + 64] = mk2(y2a, y2b);
        }
    }
}

/* ------------------------------------------------------------------ */
/* Flash v3: BQ=128, 256 threads. Q hi/lo prewritten fp16 (cp.async).  */
/* Epilogue writes swizzled fp16 A-panel for the O projection.         */
/* ------------------------------------------------------------------ */
#define PITB   272
#define KVHALF 17408
#define KVSTG  (2 * KVHALF)
#define FLASH_SMEM (2 * KVSTG)

__global__ __launch_bounds__(256) void flash_mma()
{
    extern __shared__ char sm[];
    const uint32_t sb = smem_u32(sm);
    const uint32_t QhS = sb;

    const int tid = threadIdx.x, w = tid >> 5, lane = tid & 31;
    const int qt = blockIdx.x, h = blockIdx.y, b = blockIdx.z;
    const size_t kvhead = (size_t)(b * NHEADS + h) * SSEQ;
    const float scale = 0.08838834764831845f;

    /* ---- Q hi/lo -> smem via cp.async ---- */
    {
        const char* qh_src = (const char*)(g_q16h + (kvhead + qt * 128) * HDIM);
        const char* ql_src = (const char*)(g_q16l + (kvhead + qt * 128) * HDIM);
        for (int i = tid; i < 2048; i += 256) {
            int r = i >> 4, c = i & 15;
            cp16(sb + r * PITB + c * 16, qh_src + r * 256 + c * 16);
            cp16(sb + 34816 + r * PITB + c * 16, ql_src + r * 256 + c * 16);
        }
        CP_COMMIT(); cp_wait<0>();
    }
    __syncthreads();

    uint32_t qh[8][4], ql[8][4];
#pragma unroll
    for (int kc = 0; kc < 8; kc++) {
        uint32_t addr = QhS + (uint32_t)(w * 16 + (lane & 15)) * PITB +
                        (uint32_t)((kc * 2 + (lane >> 4)) * 16);
        LDM4(qh[kc], addr);
        LDM4(ql[kc], addr + 34816);
    }
    __syncthreads();

    float O[16][4];
#pragma unroll
    for (int i = 0; i < 16; i++)
#pragma unroll
        for (int c = 0; c < 4; c++) O[i][c] = 0.f;
    float mrow0 = -INFINITY, mrow1 = -INFINITY, lrow0 = 0.f, lrow1 = 0.f;

    const int r0 = lane >> 2;
    const int ncol = (lane & 3) * 2;
    const int mg0 = qt * 128 + w * 16 + r0, mg1 = mg0 + 8;

    auto load_kv = [&](int kt, int stg) {
        const char* kb = (const char*)(g_k16 + (kvhead + kt * 64) * HDIM);
        const char* vb = (const char*)(g_v16 + (kvhead + kt * 64) * HDIM);
        uint32_t ks = sb + stg * KVSTG, vs = ks + KVHALF;
        for (int i = tid; i < 1024; i += 256) {
            int r = i >> 4, c = i & 15;
            cp16(ks + r * PITB + c * 16, kb + r * 256 + c * 16);
            cp16(vs + r * PITB + c * 16, vb + r * 256 + c * 16);
        }
    };

    const int ktmax = 2 * qt + 1;
    load_kv(0, 0); CP_COMMIT();

    for (int kt = 0; kt <= ktmax; kt++) {
        int stg = kt & 1;
        if (kt < ktmax) { load_kv(kt + 1, stg ^ 1); CP_COMMIT(); cp_wait<1>(); }
        else            { cp_wait<0>(); }
        __syncthreads();

        if (kt * 64 <= qt * 128 + w * 16 + 15) {
            const uint32_t KS = sb + stg * KVSTG, VS = KS + KVHALF;

            float s[8][4];
#pragma unroll
            for (int i = 0; i < 8; i++)
#pragma unroll
                for (int c = 0; c < 4; c++) s[i][c] = 0.f;

#pragma unroll
            for (int kc = 0; kc < 8; kc++) {
#pragma unroll
                for (int nc2 = 0; nc2 < 4; nc2++) {
                    int nrow = nc2 * 16 + ((lane >> 4) << 3) + (lane & 7);
                    int col16 = kc * 2 + ((lane >> 3) & 1);
                    uint32_t addr = KS + (uint32_t)nrow * PITB + (uint32_t)col16 * 16;
                    uint32_t k4[4];
                    LDM4(k4, addr);
                    MMAH16816(s[nc2 * 2],     qh[kc], k4[0], k4[1]);
                    MMAH16816(s[nc2 * 2],     ql[kc], k4[0], k4[1]);
                    MMAH16816(s[nc2 * 2 + 1], qh[kc], k4[2], k4[3]);
                    MMAH16816(s[nc2 * 2 + 1], ql[kc], k4[2], k4[3]);
                }
            }

            const bool crossing = (kt >= 2 * qt);
#pragma unroll
            for (int nt = 0; nt < 8; nt++) {
#pragma unroll
                for (int c = 0; c < 4; c++) s[nt][c] *= scale;
                if (crossing) {
                    int n0 = kt * 64 + nt * 8 + ncol;
                    if (n0     > mg0) s[nt][0] = -1e30f;
                    if (n0 + 1 > mg0) s[nt][1] = -1e30f;
                    if (n0     > mg1) s[nt][2] = -1e30f;
                    if (n0 + 1 > mg1) s[nt][3] = -1e30f;
                }
            }

            float mx0 = mrow0, mx1 = mrow1;
#pragma unroll
            for (int nt = 0; nt < 8; nt++) {
                mx0 = fmaxf(mx0, fmaxf(s[nt][0], s[nt][1]));
                mx1 = fmaxf(mx1, fmaxf(s[nt][2], s[nt][3]));
            }
            mx0 = fmaxf(mx0, __shfl_xor_sync(0xffffffffu, mx0, 1));
            mx0 = fmaxf(mx0, __shfl_xor_sync(0xffffffffu, mx0, 2));
            mx1 = fmaxf(mx1, __shfl_xor_sync(0xffffffffu, mx1, 1));
            mx1 = fmaxf(mx1, __shfl_xor_sync(0xffffffffu, mx1, 2));
            float a0 = __expf(mrow0 - mx0), a1 = __expf(mrow1 - mx1);
            mrow0 = mx0; mrow1 = mx1;
            float ps0 = 0.f, ps1 = 0.f;
#pragma unroll
            for (int nt = 0; nt < 8; nt++) {
                s[nt][0] = __expf(s[nt][0] - mx0);
                s[nt][1] = __expf(s[nt][1] - mx0);
                s[nt][2] = __expf(s[nt][2] - mx1);
                s[nt][3] = __expf(s[nt][3] - mx1);
                ps0 += s[nt][0] + s[nt][1];
                ps1 += s[nt][2] + s[nt][3];
            }
            ps0 += __shfl_xor_sync(0xffffffffu, ps0, 1);
            ps0 += __shfl_xor_sync(0xffffffffu, ps0, 2);
            ps1 += __shfl_xor_sync(0xffffffffu, ps1, 1);
            ps1 += __shfl_xor_sync(0xffffffffu, ps1, 2);
            lrow0 = lrow0 * a0 + ps0;
            lrow1 = lrow1 * a1 + ps1;
#pragma unroll
            for (int dn = 0; dn < 16; dn++) {
                O[dn][0] *= a0; O[dn][1] *= a0;
                O[dn][2] *= a1; O[dn][3] *= a1;
            }

#pragma unroll
            for (int pk = 0; pk < 4; pk++) {
                uint32_t pa_h[4], pa_l[4];
#pragma unroll
                for (int half = 0; half < 2; half++) {
                    int nt = pk * 2 + half;
                    __half h0 = __float2half_rn(s[nt][0]);
                    __half h1 = __float2half_rn(s[nt][1]);
                    __half h2_ = __float2half_rn(s[nt][2]);
                    __half h3 = __float2half_rn(s[nt][3]);
                    pa_h[half * 2]     = h2(h0, h1);
                    pa_h[half * 2 + 1] = h2(h2_, h3);
                    pa_l[half * 2]     = h2(__float2half_rn(s[nt][0] - __half2float(h0)),
                                            __float2half_rn(s[nt][1] - __half2float(h1)));
                    pa_l[half * 2 + 1] = h2(__float2half_rn(s[nt][2] - __half2float(h2_)),
                                            __float2half_rn(s[nt][3] - __half2float(h3)));
                }
#pragma unroll
                for (int dn2 = 0; dn2 < 8; dn2++) {
                    uint32_t addr = VS + (uint32_t)(pk * 16 + (lane & 15)) * PITB +
                                    (uint32_t)((dn2 * 2 + (lane >> 4)) * 16);
                    uint32_t v4[4];
                    LDM4T(v4, addr);
                    MMAH16816(O[dn2 * 2],     pa_h, v4[0], v4[1]);
                    MMAH16816(O[dn2 * 2],     pa_l, v4[0], v4[1]);
                    MMAH16816(O[dn2 * 2 + 1], pa_h, v4[2], v4[3]);
                    MMAH16816(O[dn2 * 2 + 1], pa_l, v4[2], v4[3]);
                }
            }
        }
        __syncthreads();
    }

    /* ---- epilogue: write swizzled fp16 A-panel for O-proj ---- */
    float il0 = 1.f / lrow0, il1 = 1.f / lrow1;
    const int mtp = b * 16 + qt;          /* panel row-tile index */
    const int r_0 = w * 16 + r0, r_1 = r_0 + 8;
#pragma unroll
    for (int dn = 0; dn < 16; dn++) {
        int d = dn * 8 + ncol;
        int kcp = 2 * h + (d >> 6);
        uint32_t cb = (uint32_t)((d & 63) * 2);
        char* base = (char*)(g_Actx + ((size_t)mtp * KC + kcp) * TILE_ELEMS);
        *(__half2*)(base + sw128((uint32_t)(r_0 * 128) + cb)) =
            mk2(O[dn][0] * il0, O[dn][1] * il0);
        *(__half2*)(base + sw128((uint32_t)(r_1 * 128) + cb)) =
            mk2(O[dn][2] * il1, O[dn][3] * il1);
    }
}

/* ------------------------------------------------------------------ */
extern "C" void kernel_launch(void* const* d_in, const int* in_sizes, int n_in,
                              void* d_out, int out_size)
{
    (void)in_sizes; (void)n_in; (void)out_size;
    const float* hs   = (const float*)d_in[0];
    const int*   pos  = (const int*)  d_in[1];
    const float* Wqkv = (const float*)d_in[2];
    const float* bqkv = (const float*)d_in[3];
    const float* Wo   = (const float*)d_in[4];
    float* out = (float*)d_out;

    __half *ahid, *actx, *bhq, *bho;
    cudaGetSymbolAddress((void**)&ahid, g_Ahid);
    cudaGetSymbolAddress((void**)&actx, g_Actx);
    cudaGetSymbolAddress((void**)&bhq,  g_BhQ);
    cudaGetSymbolAddress((void**)&bho,  g_BhO);

    cudaFuncSetAttribute(gemm_mma,
                         cudaFuncAttributeMaxDynamicSharedMemorySize, GEMM_SMEM);
    cudaFuncSetAttribute(gemm_qkv,
                         cudaFuncAttributeMaxDynamicSharedMemorySize, GEMM_SMEM);
    cudaFuncSetAttribute(flash_mma,
                         cudaFuncAttributeMaxDynamicSharedMemorySize, FLASH_SMEM);

    /* 1. rope table + packs */
    rope_table<<<TOK, 64>>>(pos);
    pack_a<<<dim3(KC, MT), 256>>>(hs, ahid);
    pack_bt<<<dim3(NTQ, KC), 256>>>(Wqkv, QKVW, bhq);

    /* 2. QKV projection, fused bias+rope+fp16 q/k/v materialization */
    gemm_qkv<<<dim3(NTQ, MT), 256, GEMM_SMEM>>>(ahid, bhq, bqkv);

    /* 3. causal flash attention -> swizzled fp16 ctx panel */
    flash_mma<<<dim3(SSEQ / 128, NHEADS, BB), 256, FLASH_SMEM>>>();

    /* 4. O projection */
    pack_bt<<<dim3(NTO, KC), 256>>>(Wo, HIDDEN, bho);
    gemm_mma<<<dim3(NTO, MT), 256, GEMM_SMEM>>>(actx, bho, out, HIDDEN);
}